// round 13
// baseline (speedup 1.0000x reference)
#include <cuda_runtime.h>
#include <cuda_fp16.h>
#include <math.h>
#include <stdint.h>

#define DIM   4096
#define NH    32
#define HD    128
#define BSZ   2
#define SEQ   2048
#define NTOK  (BSZ*SEQ)          // 4096 tokens

// ---------------- scratch (allocation-free: __device__ globals) -------------
__device__ __half g_xt [(size_t)NTOK * DIM];   // fp16+perm gemm A operand (x, then attn-out)
__device__ __half g_wqt[(size_t)DIM * DIM];    // fp16+perm weights
__device__ __half g_wkt[(size_t)DIM * DIM];
__device__ __half g_wvt[(size_t)DIM * DIM];
__device__ __half g_wot[(size_t)DIM * DIM];
__device__ __half g_qh [(size_t)NTOK * DIM];   // fp16 rotated Q, d-perm  [b,s,h,d]
__device__ __half g_kh [(size_t)NTOK * DIM];   // fp16 rotated K, d-perm  [b,s,h,d]
__device__ __half g_vt [(size_t)NTOK * DIM];   // fp16 V transposed, s-perm [b,h,d,s]

// ============================================================================
// helpers
// ============================================================================
__device__ __forceinline__ uint32_t smem_u32(const void* p) {
    uint32_t a;
    asm("{ .reg .u64 t; cvta.to.shared.u64 t, %1; cvt.u32.u64 %0, t; }"
        : "=r"(a) : "l"(p));
    return a;
}

__device__ __forceinline__ void cp16(uint32_t dst, const void* src) {
    asm volatile("cp.async.cg.shared.global [%0], [%1], 16;" :: "r"(dst), "l"(src));
}
#define CP_COMMIT() asm volatile("cp.async.commit_group;" ::: "memory")
#define CP_WAIT0()  asm volatile("cp.async.wait_group 0;"  ::: "memory")
#define CP_WAIT1()  asm volatile("cp.async.wait_group 1;"  ::: "memory")

__device__ __forceinline__ uint32_t pack_h2(float a, float b) {
    __half2 h = __floats2half2_rn(a, b);
    return *(uint32_t*)&h;
}

// fp16 m16n8k16, fp32 accumulate
__device__ __forceinline__ void mma16n8k16h(float* c, const uint32_t* a, const uint32_t* b) {
    asm volatile(
        "mma.sync.aligned.m16n8k16.row.col.f32.f16.f16.f32 "
        "{%0,%1,%2,%3}, {%4,%5,%6,%7}, {%8,%9}, {%0,%1,%2,%3};"
        : "+f"(c[0]), "+f"(c[1]), "+f"(c[2]), "+f"(c[3])
        : "r"(a[0]), "r"(a[1]), "r"(a[2]), "r"(a[3]), "r"(b[0]), "r"(b[1]));
}

// ============================================================================
// fp32 -> fp16 (rne) + k-group permutation, 5 tensors in ONE launch
// (blockIdx.y selects the tensor). 16-group [l0..l15] -> halves
// [l0,l1,l8,l9, l2,l3,l10,l11, ...]: fragment pair = one aligned float2.
// ============================================================================
__global__ __launch_bounds__(256) void cvt_h5(
    const float4* __restrict__ i0, const float4* __restrict__ i1,
    const float4* __restrict__ i2, const float4* __restrict__ i3,
    const float4* __restrict__ i4,
    uint4* __restrict__ o0, uint4* __restrict__ o1, uint4* __restrict__ o2,
    uint4* __restrict__ o3, uint4* __restrict__ o4, int n16) {
    const int z = blockIdx.y;
    const float4* in = (z == 0) ? i0 : (z == 1) ? i1 : (z == 2) ? i2 : (z == 3) ? i3 : i4;
    uint4* out       = (z == 0) ? o0 : (z == 1) ? o1 : (z == 2) ? o2 : (z == 3) ? o3 : o4;
    int i = blockIdx.x * blockDim.x + threadIdx.x;
    if (i < n16) {
        float4 v0 = in[4 * i], v1 = in[4 * i + 1], v2 = in[4 * i + 2], v3 = in[4 * i + 3];
        uint4 q0, q1;
        q0.x = pack_h2(v0.x, v0.y); q0.y = pack_h2(v2.x, v2.y);
        q0.z = pack_h2(v0.z, v0.w); q0.w = pack_h2(v2.z, v2.w);
        q1.x = pack_h2(v1.x, v1.y); q1.y = pack_h2(v3.x, v3.y);
        q1.z = pack_h2(v1.z, v1.w); q1.w = pack_h2(v3.z, v3.w);
        out[2 * i]     = q0;
        out[2 * i + 1] = q1;
    }
}

// perm of index l within a 16-group: pair p=l/2 -> uint32 slot 2*(p&3)+(p>>2)
__device__ __forceinline__ int perm16(int l) {
    int p = l >> 1;
    return 4 * (p & 3) + 2 * (p >> 2) + (l & 1);
}

// ============================================================================
// V transpose: cache_v fp32 [b,s,h,d] -> g_vt fp16 [b,h,d,s] with s-perm.
// ============================================================================
__global__ __launch_bounds__(256) void vtrans(const float* __restrict__ V,
                                              __half* __restrict__ Vt) {
    __shared__ __half tile[32][33];
    const int tx = threadIdx.x & 31, ty = threadIdx.x >> 5;   // 32 x 8
    const int s0 = blockIdx.x * 32;
    const int d0 = blockIdx.y * 32;
    const int h  = blockIdx.z & (NH - 1);
    const int b  = blockIdx.z >> 5;
#pragma unroll
    for (int j = 0; j < 4; j++) {
        int s = s0 + ty + j * 8;
        tile[ty + j * 8][tx] = __float2half_rn(V[((size_t)((b * SEQ + s) * NH + h)) * HD + d0 + tx]);
    }
    __syncthreads();
    const int sp = s0 + (tx & 16) + perm16(tx & 15);          // permuted s position
#pragma unroll
    for (int j = 0; j < 4; j++) {
        int d = d0 + ty + j * 8;
        Vt[((size_t)((b * NH + h) * HD + d)) * SEQ + sp] = tile[tx][ty + j * 8];
    }
}

// ============================================================================
// fp16 mma.sync GEMM (NT): C[m,n] = sum_k A[m,k]*B[n,k]
// CTA 256x128, 8 warps (4x2), warp tile 64x64, BK=64 halves (4 k16 steps),
// 2-stage cp.async pipeline (wait0 + sync before overwrite; one tile of
// compute ~1700cyc hides the load). Stride 80 halves: conflict-free frags.
// mode: 0 = plain fp32 C (WO) | 1 = Q: perm-fp16 H only | 2 = K: fp32 C +
//       perm-fp16 H | 3 = V: fp32 C (fp16-rounded)
// ============================================================================
#define GTM 256
#define GTN 128
#define GBK 64
#define GTS 80
#define GST 2
#define GNKI (DIM / GBK)                                   // 64
#define G_STAGE ((GTM + GTN) * GTS)                        // halves per stage
#define G_SMEM (GST * G_STAGE * 2)                         // 122880 B

__global__ __launch_bounds__(256, 1) void gemm_mma(
    const __half* __restrict__ A,
    const __half* __restrict__ B0, const __half* __restrict__ B1, const __half* __restrict__ B2,
    float* __restrict__ C0, float* __restrict__ C1, float* __restrict__ C2,
    __half* __restrict__ H0, __half* __restrict__ H1,
    const float* __restrict__ rcs, const float* __restrict__ rsn, int is_qkv) {
    extern __shared__ __half smh[];

    const int z = blockIdx.z;
    const __half* B = (z == 0) ? B0 : ((z == 1) ? B1 : B2);
    float*        C = (z == 0) ? C0 : ((z == 1) ? C1 : C2);
    __half*       H = (z == 0) ? H0 : ((z == 1) ? H1 : nullptr);
    const int  mode = is_qkv ? (z + 1) : 0;
    const bool do_rope = is_qkv && (z < 2);

    const int t    = threadIdx.x;
    const int lane = t & 31;
    const int w    = t >> 5;
    const int wm   = w >> 1;          // 0..3
    const int wn   = w & 1;           // 0..1
    const int g    = lane >> 2;       // 0..7
    const int q    = lane & 3;        // 0..3
    const int bm   = blockIdx.y, bn = blockIdx.x;

    const uint32_t sS = smem_u32(smh);
    const int lr  = t >> 2;           // 0..63
    const int lc16 = (t & 3) * 16;    // half offset 0,16,32,48
    const __half* Agp = A + (size_t)(bm * GTM + lr) * DIM + lc16;
    const __half* Bgp = B + (size_t)(bn * GTN + lr) * DIM + lc16;

    float acc[4][8][4];
#pragma unroll
    for (int i = 0; i < 4; i++)
#pragma unroll
        for (int j = 0; j < 8; j++)
#pragma unroll
            for (int v = 0; v < 4; v++) acc[i][j][v] = 0.f;

    // prologue: stage 0
    {
        const uint32_t dA = sS;
        const uint32_t dB = dA + GTM * GTS * 2;
#pragma unroll
        for (int j = 0; j < 4; j++) {
            cp16(dA + ((lr + j * 64) * GTS + lc16) * 2,     Agp + (size_t)(j * 64) * DIM);
            cp16(dA + ((lr + j * 64) * GTS + lc16 + 8) * 2, Agp + (size_t)(j * 64) * DIM + 8);
        }
#pragma unroll
        for (int j = 0; j < 2; j++) {
            cp16(dB + ((lr + j * 64) * GTS + lc16) * 2,     Bgp + (size_t)(j * 64) * DIM);
            cp16(dB + ((lr + j * 64) * GTS + lc16 + 8) * 2, Bgp + (size_t)(j * 64) * DIM + 8);
        }
        CP_COMMIT();
    }

    for (int i = 0; i < GNKI; i++) {
        CP_WAIT0();          // stage i landed
        __syncthreads();     // all warps done with stage i-1 (safe to overwrite)

        if (i + 1 < GNKI) {
            const int st = (i + 1) & 1;
            const int k0 = (i + 1) * GBK;
            const uint32_t dA = sS + st * (G_STAGE * 2);
            const uint32_t dB = dA + GTM * GTS * 2;
#pragma unroll
            for (int j = 0; j < 4; j++) {
                cp16(dA + ((lr + j * 64) * GTS + lc16) * 2,     Agp + (size_t)(j * 64) * DIM + k0);
                cp16(dA + ((lr + j * 64) * GTS + lc16 + 8) * 2, Agp + (size_t)(j * 64) * DIM + k0 + 8);
            }
#pragma unroll
            for (int j = 0; j < 2; j++) {
                cp16(dB + ((lr + j * 64) * GTS + lc16) * 2,     Bgp + (size_t)(j * 64) * DIM + k0);
                cp16(dB + ((lr + j * 64) * GTS + lc16 + 8) * 2, Bgp + (size_t)(j * 64) * DIM + k0 + 8);
            }
        }
        CP_COMMIT();   // empty in tail: keeps group accounting valid

        const __half* Ab = smh + (i & 1) * G_STAGE;
        const __half* Bb = Ab + GTM * GTS;
#pragma unroll
        for (int s = 0; s < 4; s++) {
            const int ks = s * 16 + 4 * q;        // permuted slot of (2q,2q+1,2q+8,2q+9)
            uint32_t af[4][4], bf[8][2];
#pragma unroll
            for (int mt = 0; mt < 4; mt++) {
                const int r0 = wm * 64 + mt * 16 + g;
                float2 u0 = *(const float2*)(Ab + r0 * GTS + ks);
                float2 u1 = *(const float2*)(Ab + (r0 + 8) * GTS + ks);
                af[mt][0] = __float_as_uint(u0.x);
                af[mt][1] = __float_as_uint(u1.x);
                af[mt][2] = __float_as_uint(u0.y);
                af[mt][3] = __float_as_uint(u1.y);
            }
#pragma unroll
            for (int nt = 0; nt < 8; nt++) {
                const int c0 = wn * 64 + nt * 8 + g;
                float2 v = *(const float2*)(Bb + c0 * GTS + ks);
                bf[nt][0] = __float_as_uint(v.x);
                bf[nt][1] = __float_as_uint(v.y);
            }
#pragma unroll
            for (int mt = 0; mt < 4; mt++)
#pragma unroll
                for (int nt = 0; nt < 8; nt++)
                    mma16n8k16h(acc[mt][nt], af[mt], bf[nt]);
        }
    }

    // epilogue (fused RoPE for Q/K; per-mode fp32/perm-fp16 stores)
#pragma unroll
    for (int mt = 0; mt < 4; mt++) {
        const size_t row = (size_t)bm * GTM + wm * 64 + mt * 16 + g;
#pragma unroll
        for (int nt = 0; nt < 8; nt++) {
            const int col = bn * GTN + wn * 64 + nt * 8 + q * 2;
            float2 v0 = {acc[mt][nt][0], acc[mt][nt][1]};
            float2 v1 = {acc[mt][nt][2], acc[mt][nt][3]};
            if (do_rope) {
                const int fi = (col & 127) >> 1;
                const int s0 = (int)(row & (SEQ - 1));
                const int s1 = (int)((row + 8) & (SEQ - 1));
                float c0 = rcs[s0 * 64 + fi], sn0 = rsn[s0 * 64 + fi];
                float c1 = rcs[s1 * 64 + fi], sn1 = rsn[s1 * 64 + fi];
                float2 r0 = {v0.x * c0 - v0.y * sn0, v0.x * sn0 + v0.y * c0};
                float2 r1 = {v1.x * c1 - v1.y * sn1, v1.x * sn1 + v1.y * c1};
                v0 = r0; v1 = r1;
            }
            if (mode == 0) {
                *(float2*)(C + row * DIM + col)       = v0;
                *(float2*)(C + (row + 8) * DIM + col) = v1;
            } else {
                __half2 h0 = __floats2half2_rn(v0.x, v0.y);
                __half2 h1 = __floats2half2_rn(v1.x, v1.y);
                if (mode != 3) {   // Q or K: perm-fp16 copy
                    const size_t pcol = (size_t)(col & ~15) + 4 * q + 2 * (nt & 1);
                    *(__half2*)(H + row * DIM + pcol)       = h0;
                    *(__half2*)(H + (row + 8) * DIM + pcol) = h1;
                }
                if (mode != 1) {   // K or V: fp32 cache (fp16-rounded values)
                    float2 f0 = {__low2float(h0), __high2float(h0)};
                    float2 f1 = {__low2float(h1), __high2float(h1)};
                    *(float2*)(C + row * DIM + col)       = f0;
                    *(float2*)(C + (row + 8) * DIM + col) = f1;
                }
            }
        }
    }
}

// ============================================================================
// fp16 flash attention (m16n8k16), all-perm layout: every fragment load is
// one LDS.64. BQ=128, BK=64, 8 warps. Output written perm-fp16 straight into
// the WO GEMM's A buffer.
// ============================================================================
#define ABQ 128
#define ABK 64
#define QSH 144
#define VTS 80
#define PSH 80
#define FA_SMEM ((ABQ*QSH + 2*ABK*QSH + HD*VTS + 8*16*PSH) * 2)   // 114688 B

__global__ __launch_bounds__(256, 1) void flash_mma(const __half* __restrict__ Qh,
                                                    const __half* __restrict__ Kh,
                                                    const __half* __restrict__ Vt,
                                                    __half* __restrict__ Xt) {
    extern __shared__ __half smA[];
    __half* Qs = smA;                            // 128 x 144
    __half* Kb = Qs + ABQ * QSH;                 // 2 x (64 x 144)
    __half* Vs = Kb + 2 * ABK * QSH;             // 128(d) x 80
    __half* Ps = Vs + HD * VTS;                  // 8 warps x 16 x 80

    const int t    = threadIdx.x;
    const int w    = t >> 5;
    const int lane = t & 31;
    const int g    = lane >> 2;
    const int q    = lane & 3;
    const int qt   = gridDim.x - 1 - blockIdx.x;   // longest tiles first
    const int h    = blockIdx.y, b = blockIdx.z;
    const float scale = 0.08838834764831845f;      // 1/sqrt(128)

    const uint32_t sQs = smem_u32(Qs);
    const uint32_t sKb = smem_u32(Kb);
    const uint32_t sVs = smem_u32(Vs);
    const int nkb = 2 * (qt + 1);

    auto issueK = [&](int kb, int buf) {
        const uint32_t base = sKb + (uint32_t)buf * (ABK * QSH * 2);
        for (int i = t; i < ABK * 16; i += 256) {
            int row = i >> 4, c = i & 15;
            size_t gk = ((size_t)((b * SEQ + kb * ABK + row) * NH + h)) * HD + c * 8;
            cp16(base + (row * QSH + c * 8) * 2, Kh + gk);
        }
    };
    auto issueV = [&](int kb) {
        for (int i = t; i < HD * 8; i += 256) {
            int d = i >> 3, c = i & 7;
            size_t gv = ((size_t)((b * NH + h) * HD + d)) * SEQ + kb * ABK + c * 8;
            cp16(sVs + (d * VTS + c * 8) * 2, Vt + gv);
        }
    };

    // prologue: group0 = K0, group1 = {V0, Q}
    issueK(0, 0); CP_COMMIT();
    issueV(0);
    for (int i = t; i < ABQ * 16; i += 256) {
        int row = i >> 4, c = i & 15;
        size_t gq = ((size_t)((b * SEQ + qt * ABQ + row) * NH + h)) * HD + c * 8;
        cp16(sQs + (row * QSH + c * 8) * 2, Qh + gq);
    }
    CP_COMMIT();

    float o[16][4];
#pragma unroll
    for (int i = 0; i < 16; i++)
#pragma unroll
        for (int v = 0; v < 4; v++) o[i][v] = 0.f;
    float mA = -INFINITY, mB = -INFINITY, lA = 0.f, lB = 0.f;

    __half* Pw = Ps + w * 16 * PSH;
    const int r0   = w * 16;
    const int rowA = qt * ABQ + r0 + g;            // rowB = rowA + 8

    for (int kb = 0; kb < nkb; kb++) {
        if (kb + 1 < nkb) issueK(kb + 1, (kb + 1) & 1);
        CP_COMMIT();
        CP_WAIT1();          // K_kb, V_kb, Q landed
        __syncthreads();

        __half* Kcur = Kb + (kb & 1) * (ABK * QSH);
        const bool full_skip = (kb * ABK > qt * ABQ + r0 + 15);
        if (!full_skip) {
            // ---- S = Q K^T : 8 k16 steps, all LDS.64 ----
            float s[8][4];
#pragma unroll
            for (int i = 0; i < 8; i++)
#pragma unroll
                for (int v = 0; v < 4; v++) s[i][v] = 0.f;
#pragma unroll
            for (int k16 = 0; k16 < 8; k16++) {
                const int ks = k16 * 16 + 4 * q;
                uint32_t a[4];
                float2 u0 = *(const float2*)(Qs + (r0 + g) * QSH + ks);
                float2 u1 = *(const float2*)(Qs + (r0 + g + 8) * QSH + ks);
                a[0] = __float_as_uint(u0.x);
                a[1] = __float_as_uint(u1.x);
                a[2] = __float_as_uint(u0.y);
                a[3] = __float_as_uint(u1.y);
#pragma unroll
                for (int nt = 0; nt < 8; nt++) {
                    float2 v = *(const float2*)(Kcur + (nt * 8 + g) * QSH + ks);
                    uint32_t bfr[2];
                    bfr[0] = __float_as_uint(v.x);
                    bfr[1] = __float_as_uint(v.y);
                    mma16n8k16h(s[nt], a, bfr);
                }
            }
            const bool need_mask = (kb * ABK + ABK - 1 > qt * ABQ + r0);
#pragma unroll
            for (int nt = 0; nt < 8; nt++) {
                const int c0 = kb * ABK + nt * 8 + 2 * q;
                s[nt][0] *= scale; s[nt][1] *= scale;
                s[nt][2] *= scale; s[nt][3] *= scale;
                if (need_mask) {
                    if (c0     > rowA)     s[nt][0] = -1e30f;
                    if (c0 + 1 > rowA)     s[nt][1] = -1e30f;
                    if (c0     > rowA + 8) s[nt][2] = -1e30f;
                    if (c0 + 1 > rowA + 8) s[nt][3] = -1e30f;
                }
            }
            float mxA = -INFINITY, mxB = -INFINITY;
#pragma unroll
            for (int nt = 0; nt < 8; nt++) {
                mxA = fmaxf(mxA, fmaxf(s[nt][0], s[nt][1]));
                mxB = fmaxf(mxB, fmaxf(s[nt][2], s[nt][3]));
            }
            mxA = fmaxf(mxA, __shfl_xor_sync(0xffffffffu, mxA, 1));
            mxA = fmaxf(mxA, __shfl_xor_sync(0xffffffffu, mxA, 2));
            mxB = fmaxf(mxB, __shfl_xor_sync(0xffffffffu, mxB, 1));
            mxB = fmaxf(mxB, __shfl_xor_sync(0xffffffffu, mxB, 2));
            const float mnA = fmaxf(mA, mxA), mnB = fmaxf(mB, mxB);
            const float aA = __expf(mA - mnA), aB = __expf(mB - mnB);
            float sumA = 0.f, sumB = 0.f;
#pragma unroll
            for (int nt = 0; nt < 8; nt++) {
                float p0 = __expf(s[nt][0] - mnA), p1 = __expf(s[nt][1] - mnA);
                float p2 = __expf(s[nt][2] - mnB), p3 = __expf(s[nt][3] - mnB);
                sumA += p0 + p1; sumB += p2 + p3;
                const int po = (nt >> 1) * 16 + 4 * q + 2 * (nt & 1);   // perm slot
                *(uint32_t*)(Pw + g * PSH + po)       = pack_h2(p0, p1);
                *(uint32_t*)(Pw + (g + 8) * PSH + po) = pack_h2(p2, p3);
            }
            sumA += __shfl_xor_sync(0xffffffffu, sumA, 1);
            sumA += __shfl_xor_sync(0xffffffffu, sumA, 2);
            sumB += __shfl_xor_sync(0xffffffffu, sumB, 1);
            sumB += __shfl_xor_sync(0xffffffffu, sumB, 2);
            lA = lA * aA + sumA;  mA = mnA;
            lB = lB * aB + sumB;  mB = mnB;
#pragma unroll
            for (int nt = 0; nt < 16; nt++) {
                o[nt][0] *= aA; o[nt][1] *= aA;
                o[nt][2] *= aB; o[nt][3] *= aB;
            }
            __syncwarp();
            // ---- O += P V : 4 k16 steps, all LDS.64 ----
#pragma unroll
            for (int k16 = 0; k16 < 4; k16++) {
                const int ks = k16 * 16 + 4 * q;
                uint32_t a[4];
                float2 u0 = *(const float2*)(Pw + g * PSH + ks);
                float2 u1 = *(const float2*)(Pw + (g + 8) * PSH + ks);
                a[0] = __float_as_uint(u0.x);
                a[1] = __float_as_uint(u1.x);
                a[2] = __float_as_uint(u0.y);
                a[3] = __float_as_uint(u1.y);
#pragma unroll
                for (int nt = 0; nt < 16; nt++) {
                    float2 v = *(const float2*)(Vs + (nt * 8 + g) * VTS + ks);
                    uint32_t bfr[2];
                    bfr[0] = __float_as_uint(v.x);
                    bfr[1] = __float_as_uint(v.y);
                    mma16n8k16h(o[nt], a, bfr);
                }
            }
        }
        __syncthreads();     // everyone done with Vs before refill

        if (kb + 1 < nkb) issueV(kb + 1);
        CP_COMMIT();
    }

    // write perm-fp16 directly into the WO GEMM's A operand
    const float invA = 1.f / lA, invB = 1.f / lB;
    const size_t baseA = ((size_t)(b * SEQ + rowA)) * DIM + h * HD;
    const size_t baseB = baseA + (size_t)8 * DIM;
#pragma unroll
    for (int ng = 0; ng < 8; ng++) {
        uint2 va = {pack_h2(o[2*ng][0] * invA, o[2*ng][1] * invA),
                    pack_h2(o[2*ng+1][0] * invA, o[2*ng+1][1] * invA)};
        uint2 vb = {pack_h2(o[2*ng][2] * invB, o[2*ng][3] * invB),
                    pack_h2(o[2*ng+1][2] * invB, o[2*ng+1][3] * invB)};
        *(uint2*)(Xt + baseA + ng * 16 + 4 * q) = va;
        *(uint2*)(Xt + baseB + ng * 16 + 4 * q) = vb;
    }
}

// ============================================================================
// launch
// ============================================================================
extern "C" void kernel_launch(void* const* d_in, const int* in_sizes, int n_in,
                              void* d_out, int out_size) {
    const float* x    = (const float*)d_in[0];
    const float* fcos = (const float*)d_in[1];
    const float* fsin = (const float*)d_in[2];
    // d_in[3] mask, d_in[4] input_idexes, d_in[5] cache_k, d_in[6] cache_v: unused
    const float* wq = (const float*)d_in[7];
    const float* wk = (const float*)d_in[8];
    const float* wv = (const float*)d_in[9];
    const float* wo = (const float*)d_in[10];

    float* out     = (float*)d_out;                               // [B,S,DIM]
    float* cache_k = (float*)d_out + (size_t)NTOK * DIM;          // [B,S,NH,HD]
    float* cache_v = (float*)d_out + (size_t)2 * NTOK * DIM;      // [B,S,NH,HD]

    __half* xt;   cudaGetSymbolAddress((void**)&xt,   g_xt);
    __half* wqt;  cudaGetSymbolAddress((void**)&wqt,  g_wqt);
    __half* wkt;  cudaGetSymbolAddress((void**)&wkt,  g_wkt);
    __half* wvt;  cudaGetSymbolAddress((void**)&wvt,  g_wvt);
    __half* wot;  cudaGetSymbolAddress((void**)&wot,  g_wot);
    __half* qh;   cudaGetSymbolAddress((void**)&qh,   g_qh);
    __half* kh;   cudaGetSymbolAddress((void**)&kh,   g_kh);
    __half* vt;   cudaGetSymbolAddress((void**)&vt,   g_vt);

    cudaFuncSetAttribute(gemm_mma,  cudaFuncAttributeMaxDynamicSharedMemorySize, G_SMEM);
    cudaFuncSetAttribute(flash_mma, cudaFuncAttributeMaxDynamicSharedMemorySize, FA_SMEM);

    const int N16 = NTOK * DIM / 16;       // 16-float groups per 64MB buffer
    const int cb = (N16 + 255) / 256;
    dim3 cg(cb, 5);
    cvt_h5<<<cg, 256>>>((const float4*)x, (const float4*)wq, (const float4*)wk,
                        (const float4*)wv, (const float4*)wo,
                        (uint4*)xt, (uint4*)wqt, (uint4*)wkt, (uint4*)wvt, (uint4*)wot,
                        N16);

    // fused QKV: z=0 -> Q (rope, perm-fp16 only), z=1 -> K (rope, fp32+perm-fp16),
    //            z=2 -> V (fp32, fp16-rounded)
    dim3 gq(DIM / GTN, NTOK / GTM, 3);     // (32, 16, 3)
    gemm_mma<<<gq, 256, G_SMEM>>>(xt, wqt, wkt, wvt,
                                  nullptr, cache_k, cache_v,
                                  qh, kh, fcos, fsin, 1);

    // V transpose -> perm-fp16 [b,h,d,s]
    dim3 vg(SEQ / 32, HD / 32, BSZ * NH);  // (64, 4, 64)
    vtrans<<<vg, 256>>>(cache_v, vt);

    // flash writes perm-fp16 attention output straight into xt
    dim3 fg(SEQ / ABQ, NH, BSZ);           // (16, 32, 2)
    flash_mma<<<fg, 256, FA_SMEM>>>(qh, kh, vt, xt);

    dim3 gw(DIM / GTN, NTOK / GTM, 1);     // (32, 16)
    gemm_mma<<<gw, 256, G_SMEM>>>(xt, wot, wot, wot,
                                  out, out, out,
                                  nullptr, nullptr, nullptr, nullptr, 0);
}

// round 14
// speedup vs baseline: 1.0393x; 1.0393x over previous
#include <cuda_runtime.h>
#include <cuda_fp16.h>
#include <math.h>
#include <stdint.h>

#define DIM   4096
#define NH    32
#define HD    128
#define BSZ   2
#define SEQ   2048
#define NTOK  (BSZ*SEQ)          // 4096 tokens

// ---------------- scratch (allocation-free: __device__ globals) -------------
__device__ __half g_xt [(size_t)NTOK * DIM];   // fp16+perm gemm A operand (x, then attn-out)
__device__ __half g_wqt[(size_t)DIM * DIM];    // fp16+perm weights
__device__ __half g_wkt[(size_t)DIM * DIM];
__device__ __half g_wvt[(size_t)DIM * DIM];
__device__ __half g_wot[(size_t)DIM * DIM];
__device__ __half g_qh [(size_t)NTOK * DIM];   // fp16 rotated Q, d-perm  [b,s,h,d]
__device__ __half g_kh [(size_t)NTOK * DIM];   // fp16 rotated K, d-perm  [b,s,h,d]
__device__ __half g_vt [(size_t)NTOK * DIM];   // fp16 V transposed, s-perm [b,h,d,s]

// ============================================================================
// helpers
// ============================================================================
__device__ __forceinline__ uint32_t smem_u32(const void* p) {
    uint32_t a;
    asm("{ .reg .u64 t; cvta.to.shared.u64 t, %1; cvt.u32.u64 %0, t; }"
        : "=r"(a) : "l"(p));
    return a;
}

__device__ __forceinline__ void cp16(uint32_t dst, const void* src) {
    asm volatile("cp.async.cg.shared.global [%0], [%1], 16;" :: "r"(dst), "l"(src));
}
#define CP_COMMIT() asm volatile("cp.async.commit_group;" ::: "memory")
#define CP_WAIT1()  asm volatile("cp.async.wait_group 1;"  ::: "memory")
#define CP_WAIT2()  asm volatile("cp.async.wait_group 2;"  ::: "memory")

__device__ __forceinline__ uint32_t pack_h2(float a, float b) {
    __half2 h = __floats2half2_rn(a, b);
    return *(uint32_t*)&h;
}

// fp16 m16n8k16, fp32 accumulate
__device__ __forceinline__ void mma16n8k16h(float* c, const uint32_t* a, const uint32_t* b) {
    asm volatile(
        "mma.sync.aligned.m16n8k16.row.col.f32.f16.f16.f32 "
        "{%0,%1,%2,%3}, {%4,%5,%6,%7}, {%8,%9}, {%0,%1,%2,%3};"
        : "+f"(c[0]), "+f"(c[1]), "+f"(c[2]), "+f"(c[3])
        : "r"(a[0]), "r"(a[1]), "r"(a[2]), "r"(a[3]), "r"(b[0]), "r"(b[1]));
}

// ============================================================================
// fp32 -> fp16 (rne) + k-group permutation, 5 tensors in ONE launch
// (blockIdx.y selects the tensor). 16-group [l0..l15] -> halves
// [l0,l1,l8,l9, l2,l3,l10,l11, ...]: fragment pair = one aligned float2.
// ============================================================================
__global__ __launch_bounds__(256) void cvt_h5(
    const float4* __restrict__ i0, const float4* __restrict__ i1,
    const float4* __restrict__ i2, const float4* __restrict__ i3,
    const float4* __restrict__ i4,
    uint4* __restrict__ o0, uint4* __restrict__ o1, uint4* __restrict__ o2,
    uint4* __restrict__ o3, uint4* __restrict__ o4, int n16) {
    const int z = blockIdx.y;
    const float4* in = (z == 0) ? i0 : (z == 1) ? i1 : (z == 2) ? i2 : (z == 3) ? i3 : i4;
    uint4* out       = (z == 0) ? o0 : (z == 1) ? o1 : (z == 2) ? o2 : (z == 3) ? o3 : o4;
    int i = blockIdx.x * blockDim.x + threadIdx.x;
    if (i < n16) {
        float4 v0 = in[4 * i], v1 = in[4 * i + 1], v2 = in[4 * i + 2], v3 = in[4 * i + 3];
        uint4 q0, q1;
        q0.x = pack_h2(v0.x, v0.y); q0.y = pack_h2(v2.x, v2.y);
        q0.z = pack_h2(v0.z, v0.w); q0.w = pack_h2(v2.z, v2.w);
        q1.x = pack_h2(v1.x, v1.y); q1.y = pack_h2(v3.x, v3.y);
        q1.z = pack_h2(v1.z, v1.w); q1.w = pack_h2(v3.z, v3.w);
        out[2 * i]     = q0;
        out[2 * i + 1] = q1;
    }
}

// perm of index l within a 16-group: pair p=l/2 -> uint32 slot 2*(p&3)+(p>>2)
__device__ __forceinline__ int perm16(int l) {
    int p = l >> 1;
    return 4 * (p & 3) + 2 * (p >> 2) + (l & 1);
}

// ============================================================================
// V transpose: cache_v fp32 [b,s,h,d] -> g_vt fp16 [b,h,d,s] with s-perm.
// ============================================================================
__global__ __launch_bounds__(256) void vtrans(const float* __restrict__ V,
                                              __half* __restrict__ Vt) {
    __shared__ __half tile[32][33];
    const int tx = threadIdx.x & 31, ty = threadIdx.x >> 5;   // 32 x 8
    const int s0 = blockIdx.x * 32;
    const int d0 = blockIdx.y * 32;
    const int h  = blockIdx.z & (NH - 1);
    const int b  = blockIdx.z >> 5;
#pragma unroll
    for (int j = 0; j < 4; j++) {
        int s = s0 + ty + j * 8;
        tile[ty + j * 8][tx] = __float2half_rn(V[((size_t)((b * SEQ + s) * NH + h)) * HD + d0 + tx]);
    }
    __syncthreads();
    const int sp = s0 + (tx & 16) + perm16(tx & 15);          // permuted s position
#pragma unroll
    for (int j = 0; j < 4; j++) {
        int d = d0 + ty + j * 8;
        Vt[((size_t)((b * NH + h) * HD + d)) * SEQ + sp] = tile[tx][ty + j * 8];
    }
}

// ============================================================================
// fp16 mma.sync GEMM (NT): C[m,n] = sum_k A[m,k]*B[n,k]
// CTA 256x128, 8 warps (4x2), warp tile 64x64, BK=32 halves, 4-stage pipe.
// (Round-12 proven config: BK=64/2-stage regressed — load latency exposed.)
// mode: 0 = plain fp32 C (WO) | 1 = Q: perm-fp16 H only | 2 = K: fp32 C +
//       perm-fp16 H | 3 = V: fp32 C (fp16-rounded)
// ============================================================================
#define GTM 256
#define GTN 128
#define GBK 32
#define GTS 48
#define GST 4
#define GNKI (DIM / GBK)                                   // 128
#define G_STAGE ((GTM + GTN) * GTS)                        // halves per stage
#define G_SMEM (GST * G_STAGE * 2)                         // 147456 B

__global__ __launch_bounds__(256, 1) void gemm_mma(
    const __half* __restrict__ A,
    const __half* __restrict__ B0, const __half* __restrict__ B1, const __half* __restrict__ B2,
    float* __restrict__ C0, float* __restrict__ C1, float* __restrict__ C2,
    __half* __restrict__ H0, __half* __restrict__ H1,
    const float* __restrict__ rcs, const float* __restrict__ rsn, int is_qkv) {
    extern __shared__ __half smh[];

    const int z = blockIdx.z;
    const __half* B = (z == 0) ? B0 : ((z == 1) ? B1 : B2);
    float*        C = (z == 0) ? C0 : ((z == 1) ? C1 : C2);
    __half*       H = (z == 0) ? H0 : ((z == 1) ? H1 : nullptr);
    const int  mode = is_qkv ? (z + 1) : 0;
    const bool do_rope = is_qkv && (z < 2);

    const int t    = threadIdx.x;
    const int lane = t & 31;
    const int w    = t >> 5;
    const int wm   = w >> 1;          // 0..3
    const int wn   = w & 1;           // 0..1
    const int g    = lane >> 2;       // 0..7
    const int q    = lane & 3;        // 0..3
    const int bm   = blockIdx.y, bn = blockIdx.x;

    const uint32_t sS = smem_u32(smh);
    const int lr  = t >> 2;           // 0..63
    const int lc8 = (t & 3) * 8;      // half offset 0,8,16,24
    const __half* Agp = A + (size_t)(bm * GTM + lr) * DIM + lc8;
    const __half* Bgp = B + (size_t)(bn * GTN + lr) * DIM + lc8;

    float acc[4][8][4];
#pragma unroll
    for (int i = 0; i < 4; i++)
#pragma unroll
        for (int j = 0; j < 8; j++)
#pragma unroll
            for (int v = 0; v < 4; v++) acc[i][j][v] = 0.f;

    // prologue: stages 0..GST-2
#pragma unroll
    for (int s = 0; s < GST - 1; s++) {
        const int k0 = s * GBK;
        const uint32_t dA = sS + s * (G_STAGE * 2);
        const uint32_t dB = dA + GTM * GTS * 2;
#pragma unroll
        for (int j = 0; j < 4; j++)
            cp16(dA + ((lr + j * 64) * GTS + lc8) * 2, Agp + (size_t)(j * 64) * DIM + k0);
#pragma unroll
        for (int j = 0; j < 2; j++)
            cp16(dB + ((lr + j * 64) * GTS + lc8) * 2, Bgp + (size_t)(j * 64) * DIM + k0);
        CP_COMMIT();
    }

    for (int i = 0; i < GNKI; i++) {
        CP_WAIT2();
        __syncthreads();

        if (i + GST - 1 < GNKI) {
            const int st = (i + GST - 1) & (GST - 1);
            const int k0 = (i + GST - 1) * GBK;
            const uint32_t dA = sS + st * (G_STAGE * 2);
            const uint32_t dB = dA + GTM * GTS * 2;
#pragma unroll
            for (int j = 0; j < 4; j++)
                cp16(dA + ((lr + j * 64) * GTS + lc8) * 2, Agp + (size_t)(j * 64) * DIM + k0);
#pragma unroll
            for (int j = 0; j < 2; j++)
                cp16(dB + ((lr + j * 64) * GTS + lc8) * 2, Bgp + (size_t)(j * 64) * DIM + k0);
        }
        CP_COMMIT();   // empty in tail: keeps group accounting valid

        const __half* Ab = smh + (i & (GST - 1)) * G_STAGE;
        const __half* Bb = Ab + GTM * GTS;
#pragma unroll
        for (int s = 0; s < 2; s++) {
            const int ks = s * 16 + 4 * q;        // permuted slot of (2q,2q+1,2q+8,2q+9)
            uint32_t af[4][4], bf[8][2];
#pragma unroll
            for (int mt = 0; mt < 4; mt++) {
                const int r0 = wm * 64 + mt * 16 + g;
                float2 u0 = *(const float2*)(Ab + r0 * GTS + ks);
                float2 u1 = *(const float2*)(Ab + (r0 + 8) * GTS + ks);
                af[mt][0] = __float_as_uint(u0.x);
                af[mt][1] = __float_as_uint(u1.x);
                af[mt][2] = __float_as_uint(u0.y);
                af[mt][3] = __float_as_uint(u1.y);
            }
#pragma unroll
            for (int nt = 0; nt < 8; nt++) {
                const int c0 = wn * 64 + nt * 8 + g;
                float2 v = *(const float2*)(Bb + c0 * GTS + ks);
                bf[nt][0] = __float_as_uint(v.x);
                bf[nt][1] = __float_as_uint(v.y);
            }
#pragma unroll
            for (int mt = 0; mt < 4; mt++)
#pragma unroll
                for (int nt = 0; nt < 8; nt++)
                    mma16n8k16h(acc[mt][nt], af[mt], bf[nt]);
        }
    }

    // epilogue (fused RoPE for Q/K; per-mode fp32/perm-fp16 stores)
#pragma unroll
    for (int mt = 0; mt < 4; mt++) {
        const size_t row = (size_t)bm * GTM + wm * 64 + mt * 16 + g;
#pragma unroll
        for (int nt = 0; nt < 8; nt++) {
            const int col = bn * GTN + wn * 64 + nt * 8 + q * 2;
            float2 v0 = {acc[mt][nt][0], acc[mt][nt][1]};
            float2 v1 = {acc[mt][nt][2], acc[mt][nt][3]};
            if (do_rope) {
                const int fi = (col & 127) >> 1;
                const int s0 = (int)(row & (SEQ - 1));
                const int s1 = (int)((row + 8) & (SEQ - 1));
                float c0 = rcs[s0 * 64 + fi], sn0 = rsn[s0 * 64 + fi];
                float c1 = rcs[s1 * 64 + fi], sn1 = rsn[s1 * 64 + fi];
                float2 r0 = {v0.x * c0 - v0.y * sn0, v0.x * sn0 + v0.y * c0};
                float2 r1 = {v1.x * c1 - v1.y * sn1, v1.x * sn1 + v1.y * c1};
                v0 = r0; v1 = r1;
            }
            if (mode == 0) {
                *(float2*)(C + row * DIM + col)       = v0;
                *(float2*)(C + (row + 8) * DIM + col) = v1;
            } else {
                __half2 h0 = __floats2half2_rn(v0.x, v0.y);
                __half2 h1 = __floats2half2_rn(v1.x, v1.y);
                if (mode != 3) {   // Q or K: perm-fp16 copy
                    const size_t pcol = (size_t)(col & ~15) + 4 * q + 2 * (nt & 1);
                    *(__half2*)(H + row * DIM + pcol)       = h0;
                    *(__half2*)(H + (row + 8) * DIM + pcol) = h1;
                }
                if (mode != 1) {   // K or V: fp32 cache (fp16-rounded values)
                    float2 f0 = {__low2float(h0), __high2float(h0)};
                    float2 f1 = {__low2float(h1), __high2float(h1)};
                    *(float2*)(C + row * DIM + col)       = f0;
                    *(float2*)(C + (row + 8) * DIM + col) = f1;
                }
            }
        }
    }
}

// ============================================================================
// fp16 flash attention (m16n8k16), all-perm layout: every fragment load is
// one LDS.64. BQ=128, BK=64, 8 warps. Output written perm-fp16 straight into
// the WO GEMM's A buffer.
// ============================================================================
#define ABQ 128
#define ABK 64
#define QSH 144
#define VTS 80
#define PSH 80
#define FA_SMEM ((ABQ*QSH + 2*ABK*QSH + HD*VTS + 8*16*PSH) * 2)   // 114688 B

__global__ __launch_bounds__(256, 1) void flash_mma(const __half* __restrict__ Qh,
                                                    const __half* __restrict__ Kh,
                                                    const __half* __restrict__ Vt,
                                                    __half* __restrict__ Xt) {
    extern __shared__ __half smA[];
    __half* Qs = smA;                            // 128 x 144
    __half* Kb = Qs + ABQ * QSH;                 // 2 x (64 x 144)
    __half* Vs = Kb + 2 * ABK * QSH;             // 128(d) x 80
    __half* Ps = Vs + HD * VTS;                  // 8 warps x 16 x 80

    const int t    = threadIdx.x;
    const int w    = t >> 5;
    const int lane = t & 31;
    const int g    = lane >> 2;
    const int q    = lane & 3;
    const int qt   = gridDim.x - 1 - blockIdx.x;   // longest tiles first
    const int h    = blockIdx.y, b = blockIdx.z;
    const float scale = 0.08838834764831845f;      // 1/sqrt(128)

    const uint32_t sQs = smem_u32(Qs);
    const uint32_t sKb = smem_u32(Kb);
    const uint32_t sVs = smem_u32(Vs);
    const int nkb = 2 * (qt + 1);

    auto issueK = [&](int kb, int buf) {
        const uint32_t base = sKb + (uint32_t)buf * (ABK * QSH * 2);
        for (int i = t; i < ABK * 16; i += 256) {
            int row = i >> 4, c = i & 15;
            size_t gk = ((size_t)((b * SEQ + kb * ABK + row) * NH + h)) * HD + c * 8;
            cp16(base + (row * QSH + c * 8) * 2, Kh + gk);
        }
    };
    auto issueV = [&](int kb) {
        for (int i = t; i < HD * 8; i += 256) {
            int d = i >> 3, c = i & 7;
            size_t gv = ((size_t)((b * NH + h) * HD + d)) * SEQ + kb * ABK + c * 8;
            cp16(sVs + (d * VTS + c * 8) * 2, Vt + gv);
        }
    };

    // prologue: group0 = K0, group1 = {V0, Q}
    issueK(0, 0); CP_COMMIT();
    issueV(0);
    for (int i = t; i < ABQ * 16; i += 256) {
        int row = i >> 4, c = i & 15;
        size_t gq = ((size_t)((b * SEQ + qt * ABQ + row) * NH + h)) * HD + c * 8;
        cp16(sQs + (row * QSH + c * 8) * 2, Qh + gq);
    }
    CP_COMMIT();

    float o[16][4];
#pragma unroll
    for (int i = 0; i < 16; i++)
#pragma unroll
        for (int v = 0; v < 4; v++) o[i][v] = 0.f;
    float mA = -INFINITY, mB = -INFINITY, lA = 0.f, lB = 0.f;

    __half* Pw = Ps + w * 16 * PSH;
    const int r0   = w * 16;
    const int rowA = qt * ABQ + r0 + g;            // rowB = rowA + 8

    for (int kb = 0; kb < nkb; kb++) {
        if (kb + 1 < nkb) issueK(kb + 1, (kb + 1) & 1);
        CP_COMMIT();
        CP_WAIT1();          // K_kb, V_kb, Q landed
        __syncthreads();

        __half* Kcur = Kb + (kb & 1) * (ABK * QSH);
        const bool full_skip = (kb * ABK > qt * ABQ + r0 + 15);
        if (!full_skip) {
            // ---- S = Q K^T : 8 k16 steps, all LDS.64 ----
            float s[8][4];
#pragma unroll
            for (int i = 0; i < 8; i++)
#pragma unroll
                for (int v = 0; v < 4; v++) s[i][v] = 0.f;
#pragma unroll
            for (int k16 = 0; k16 < 8; k16++) {
                const int ks = k16 * 16 + 4 * q;
                uint32_t a[4];
                float2 u0 = *(const float2*)(Qs + (r0 + g) * QSH + ks);
                float2 u1 = *(const float2*)(Qs + (r0 + g + 8) * QSH + ks);
                a[0] = __float_as_uint(u0.x);
                a[1] = __float_as_uint(u1.x);
                a[2] = __float_as_uint(u0.y);
                a[3] = __float_as_uint(u1.y);
#pragma unroll
                for (int nt = 0; nt < 8; nt++) {
                    float2 v = *(const float2*)(Kcur + (nt * 8 + g) * QSH + ks);
                    uint32_t bfr[2];
                    bfr[0] = __float_as_uint(v.x);
                    bfr[1] = __float_as_uint(v.y);
                    mma16n8k16h(s[nt], a, bfr);
                }
            }
            const bool need_mask = (kb * ABK + ABK - 1 > qt * ABQ + r0);
#pragma unroll
            for (int nt = 0; nt < 8; nt++) {
                const int c0 = kb * ABK + nt * 8 + 2 * q;
                s[nt][0] *= scale; s[nt][1] *= scale;
                s[nt][2] *= scale; s[nt][3] *= scale;
                if (need_mask) {
                    if (c0     > rowA)     s[nt][0] = -1e30f;
                    if (c0 + 1 > rowA)     s[nt][1] = -1e30f;
                    if (c0     > rowA + 8) s[nt][2] = -1e30f;
                    if (c0 + 1 > rowA + 8) s[nt][3] = -1e30f;
                }
            }
            float mxA = -INFINITY, mxB = -INFINITY;
#pragma unroll
            for (int nt = 0; nt < 8; nt++) {
                mxA = fmaxf(mxA, fmaxf(s[nt][0], s[nt][1]));
                mxB = fmaxf(mxB, fmaxf(s[nt][2], s[nt][3]));
            }
            mxA = fmaxf(mxA, __shfl_xor_sync(0xffffffffu, mxA, 1));
            mxA = fmaxf(mxA, __shfl_xor_sync(0xffffffffu, mxA, 2));
            mxB = fmaxf(mxB, __shfl_xor_sync(0xffffffffu, mxB, 1));
            mxB = fmaxf(mxB, __shfl_xor_sync(0xffffffffu, mxB, 2));
            const float mnA = fmaxf(mA, mxA), mnB = fmaxf(mB, mxB);
            const float aA = __expf(mA - mnA), aB = __expf(mB - mnB);
            float sumA = 0.f, sumB = 0.f;
#pragma unroll
            for (int nt = 0; nt < 8; nt++) {
                float p0 = __expf(s[nt][0] - mnA), p1 = __expf(s[nt][1] - mnA);
                float p2 = __expf(s[nt][2] - mnB), p3 = __expf(s[nt][3] - mnB);
                sumA += p0 + p1; sumB += p2 + p3;
                const int po = (nt >> 1) * 16 + 4 * q + 2 * (nt & 1);   // perm slot
                *(uint32_t*)(Pw + g * PSH + po)       = pack_h2(p0, p1);
                *(uint32_t*)(Pw + (g + 8) * PSH + po) = pack_h2(p2, p3);
            }
            sumA += __shfl_xor_sync(0xffffffffu, sumA, 1);
            sumA += __shfl_xor_sync(0xffffffffu, sumA, 2);
            sumB += __shfl_xor_sync(0xffffffffu, sumB, 1);
            sumB += __shfl_xor_sync(0xffffffffu, sumB, 2);
            lA = lA * aA + sumA;  mA = mnA;
            lB = lB * aB + sumB;  mB = mnB;
#pragma unroll
            for (int nt = 0; nt < 16; nt++) {
                o[nt][0] *= aA; o[nt][1] *= aA;
                o[nt][2] *= aB; o[nt][3] *= aB;
            }
            __syncwarp();
            // ---- O += P V : 4 k16 steps, all LDS.64 ----
#pragma unroll
            for (int k16 = 0; k16 < 4; k16++) {
                const int ks = k16 * 16 + 4 * q;
                uint32_t a[4];
                float2 u0 = *(const float2*)(Pw + g * PSH + ks);
                float2 u1 = *(const float2*)(Pw + (g + 8) * PSH + ks);
                a[0] = __float_as_uint(u0.x);
                a[1] = __float_as_uint(u1.x);
                a[2] = __float_as_uint(u0.y);
                a[3] = __float_as_uint(u1.y);
#pragma unroll
                for (int nt = 0; nt < 16; nt++) {
                    float2 v = *(const float2*)(Vs + (nt * 8 + g) * VTS + ks);
                    uint32_t bfr[2];
                    bfr[0] = __float_as_uint(v.x);
                    bfr[1] = __float_as_uint(v.y);
                    mma16n8k16h(o[nt], a, bfr);
                }
            }
        }
        __syncthreads();     // everyone done with Vs before refill

        if (kb + 1 < nkb) issueV(kb + 1);
        CP_COMMIT();
    }

    // write perm-fp16 directly into the WO GEMM's A operand
    const float invA = 1.f / lA, invB = 1.f / lB;
    const size_t baseA = ((size_t)(b * SEQ + rowA)) * DIM + h * HD;
    const size_t baseB = baseA + (size_t)8 * DIM;
#pragma unroll
    for (int ng = 0; ng < 8; ng++) {
        uint2 va = {pack_h2(o[2*ng][0] * invA, o[2*ng][1] * invA),
                    pack_h2(o[2*ng+1][0] * invA, o[2*ng+1][1] * invA)};
        uint2 vb = {pack_h2(o[2*ng][2] * invB, o[2*ng][3] * invB),
                    pack_h2(o[2*ng+1][2] * invB, o[2*ng+1][3] * invB)};
        *(uint2*)(Xt + baseA + ng * 16 + 4 * q) = va;
        *(uint2*)(Xt + baseB + ng * 16 + 4 * q) = vb;
    }
}

// ============================================================================
// launch
// ============================================================================
extern "C" void kernel_launch(void* const* d_in, const int* in_sizes, int n_in,
                              void* d_out, int out_size) {
    const float* x    = (const float*)d_in[0];
    const float* fcos = (const float*)d_in[1];
    const float* fsin = (const float*)d_in[2];
    // d_in[3] mask, d_in[4] input_idexes, d_in[5] cache_k, d_in[6] cache_v: unused
    const float* wq = (const float*)d_in[7];
    const float* wk = (const float*)d_in[8];
    const float* wv = (const float*)d_in[9];
    const float* wo = (const float*)d_in[10];

    float* out     = (float*)d_out;                               // [B,S,DIM]
    float* cache_k = (float*)d_out + (size_t)NTOK * DIM;          // [B,S,NH,HD]
    float* cache_v = (float*)d_out + (size_t)2 * NTOK * DIM;      // [B,S,NH,HD]

    __half* xt;   cudaGetSymbolAddress((void**)&xt,   g_xt);
    __half* wqt;  cudaGetSymbolAddress((void**)&wqt,  g_wqt);
    __half* wkt;  cudaGetSymbolAddress((void**)&wkt,  g_wkt);
    __half* wvt;  cudaGetSymbolAddress((void**)&wvt,  g_wvt);
    __half* wot;  cudaGetSymbolAddress((void**)&wot,  g_wot);
    __half* qh;   cudaGetSymbolAddress((void**)&qh,   g_qh);
    __half* kh;   cudaGetSymbolAddress((void**)&kh,   g_kh);
    __half* vt;   cudaGetSymbolAddress((void**)&vt,   g_vt);

    cudaFuncSetAttribute(gemm_mma,  cudaFuncAttributeMaxDynamicSharedMemorySize, G_SMEM);
    cudaFuncSetAttribute(flash_mma, cudaFuncAttributeMaxDynamicSharedMemorySize, FA_SMEM);

    const int N16 = NTOK * DIM / 16;       // 16-float groups per 64MB buffer
    const int cb = (N16 + 255) / 256;
    dim3 cg(cb, 5);
    cvt_h5<<<cg, 256>>>((const float4*)x, (const float4*)wq, (const float4*)wk,
                        (const float4*)wv, (const float4*)wo,
                        (uint4*)xt, (uint4*)wqt, (uint4*)wkt, (uint4*)wvt, (uint4*)wot,
                        N16);

    // fused QKV: z=0 -> Q (rope, perm-fp16 only), z=1 -> K (rope, fp32+perm-fp16),
    //            z=2 -> V (fp32, fp16-rounded)
    dim3 gq(DIM / GTN, NTOK / GTM, 3);     // (32, 16, 3)
    gemm_mma<<<gq, 256, G_SMEM>>>(xt, wqt, wkt, wvt,
                                  nullptr, cache_k, cache_v,
                                  qh, kh, fcos, fsin, 1);

    // V transpose -> perm-fp16 [b,h,d,s]
    dim3 vg(SEQ / 32, HD / 32, BSZ * NH);  // (64, 4, 64)
    vtrans<<<vg, 256>>>(cache_v, vt);

    // flash writes perm-fp16 attention output straight into xt
    dim3 fg(SEQ / ABQ, NH, BSZ);           // (16, 32, 2)
    flash_mma<<<fg, 256, FA_SMEM>>>(qh, kh, vt, xt);

    dim3 gw(DIM / GTN, NTOK / GTM, 1);     // (32, 16)
    gemm_mma<<<gw, 256, G_SMEM>>>(xt, wot, wot, wot,
                                  out, out, out,
                                  nullptr, nullptr, nullptr, nullptr, 0);
}

// round 15
// speedup vs baseline: 1.0492x; 1.0095x over previous
#include <cuda_runtime.h>
#include <cuda_fp16.h>
#include <math.h>
#include <stdint.h>

#define DIM   4096
#define NH    32
#define HD    128
#define BSZ   2
#define SEQ   2048
#define NTOK  (BSZ*SEQ)          // 4096 tokens

// ---------------- scratch (allocation-free: __device__ globals) -------------
__device__ __half g_xt [(size_t)NTOK * DIM];   // fp16+perm gemm A operand (x, then attn-out)
__device__ __half g_wqt[(size_t)DIM * DIM];    // fp16+perm weights
__device__ __half g_wkt[(size_t)DIM * DIM];
__device__ __half g_wvt[(size_t)DIM * DIM];
__device__ __half g_wot[(size_t)DIM * DIM];
__device__ __half g_qh [(size_t)NTOK * DIM];   // fp16 rotated Q, d-perm  [b,s,h,d]
__device__ __half g_kh [(size_t)NTOK * DIM];   // fp16 rotated K, d-perm  [b,s,h,d]
__device__ __half g_vt [(size_t)NTOK * DIM];   // fp16 V transposed, s-perm [b,h,d,s]

// ============================================================================
// helpers
// ============================================================================
__device__ __forceinline__ uint32_t smem_u32(const void* p) {
    uint32_t a;
    asm("{ .reg .u64 t; cvta.to.shared.u64 t, %1; cvt.u32.u64 %0, t; }"
        : "=r"(a) : "l"(p));
    return a;
}

__device__ __forceinline__ void cp16(uint32_t dst, const void* src) {
    asm volatile("cp.async.cg.shared.global [%0], [%1], 16;" :: "r"(dst), "l"(src));
}
#define CP_COMMIT() asm volatile("cp.async.commit_group;" ::: "memory")
#define CP_WAIT1()  asm volatile("cp.async.wait_group 1;"  ::: "memory")
#define CP_WAIT2()  asm volatile("cp.async.wait_group 2;"  ::: "memory")

__device__ __forceinline__ uint32_t pack_h2(float a, float b) {
    __half2 h = __floats2half2_rn(a, b);
    return *(uint32_t*)&h;
}

// fp16 m16n8k16, fp32 accumulate
__device__ __forceinline__ void mma16n8k16h(float* c, const uint32_t* a, const uint32_t* b) {
    asm volatile(
        "mma.sync.aligned.m16n8k16.row.col.f32.f16.f16.f32 "
        "{%0,%1,%2,%3}, {%4,%5,%6,%7}, {%8,%9}, {%0,%1,%2,%3};"
        : "+f"(c[0]), "+f"(c[1]), "+f"(c[2]), "+f"(c[3])
        : "r"(a[0]), "r"(a[1]), "r"(a[2]), "r"(a[3]), "r"(b[0]), "r"(b[1]));
}

// ============================================================================
// fp32 -> fp16 (rne) + k-group permutation, 5 tensors in ONE launch
// (blockIdx.y selects the tensor). 16-group [l0..l15] -> halves
// [l0,l1,l8,l9, l2,l3,l10,l11, ...]: fragment pair = one aligned float2.
// ============================================================================
__global__ __launch_bounds__(256) void cvt_h5(
    const float4* __restrict__ i0, const float4* __restrict__ i1,
    const float4* __restrict__ i2, const float4* __restrict__ i3,
    const float4* __restrict__ i4,
    uint4* __restrict__ o0, uint4* __restrict__ o1, uint4* __restrict__ o2,
    uint4* __restrict__ o3, uint4* __restrict__ o4, int n16) {
    const int z = blockIdx.y;
    const float4* in = (z == 0) ? i0 : (z == 1) ? i1 : (z == 2) ? i2 : (z == 3) ? i3 : i4;
    uint4* out       = (z == 0) ? o0 : (z == 1) ? o1 : (z == 2) ? o2 : (z == 3) ? o3 : o4;
    int i = blockIdx.x * blockDim.x + threadIdx.x;
    if (i < n16) {
        float4 v0 = in[4 * i], v1 = in[4 * i + 1], v2 = in[4 * i + 2], v3 = in[4 * i + 3];
        uint4 q0, q1;
        q0.x = pack_h2(v0.x, v0.y); q0.y = pack_h2(v2.x, v2.y);
        q0.z = pack_h2(v0.z, v0.w); q0.w = pack_h2(v2.z, v2.w);
        q1.x = pack_h2(v1.x, v1.y); q1.y = pack_h2(v3.x, v3.y);
        q1.z = pack_h2(v1.z, v1.w); q1.w = pack_h2(v3.z, v3.w);
        out[2 * i]     = q0;
        out[2 * i + 1] = q1;
    }
}

// perm of index l within a 16-group: pair p=l/2 -> uint32 slot 2*(p&3)+(p>>2)
__device__ __forceinline__ int perm16(int l) {
    int p = l >> 1;
    return 4 * (p & 3) + 2 * (p >> 2) + (l & 1);
}

// ============================================================================
// V transpose: cache_v fp32 [b,s,h,d] -> g_vt fp16 [b,h,d,s] with s-perm.
// ============================================================================
__global__ __launch_bounds__(256) void vtrans(const float* __restrict__ V,
                                              __half* __restrict__ Vt) {
    __shared__ __half tile[32][33];
    const int tx = threadIdx.x & 31, ty = threadIdx.x >> 5;   // 32 x 8
    const int s0 = blockIdx.x * 32;
    const int d0 = blockIdx.y * 32;
    const int h  = blockIdx.z & (NH - 1);
    const int b  = blockIdx.z >> 5;
#pragma unroll
    for (int j = 0; j < 4; j++) {
        int s = s0 + ty + j * 8;
        tile[ty + j * 8][tx] = __float2half_rn(V[((size_t)((b * SEQ + s) * NH + h)) * HD + d0 + tx]);
    }
    __syncthreads();
    const int sp = s0 + (tx & 16) + perm16(tx & 15);          // permuted s position
#pragma unroll
    for (int j = 0; j < 4; j++) {
        int d = d0 + ty + j * 8;
        Vt[((size_t)((b * NH + h) * HD + d)) * SEQ + sp] = tile[tx][ty + j * 8];
    }
}

// ============================================================================
// fp16 mma.sync GEMM (NT): C[m,n] = sum_k A[m,k]*B[n,k]
// CTA 256x128, 8 warps (4x2), warp tile 64x64, BK=32 halves, 4-stage pipe.
// mode: 0 = plain fp32 C (WO) | 1 = Q: perm-fp16 H only | 2 = K: fp32 C +
//       perm-fp16 H | 3 = V: fp32 C (fp16-rounded)
// ============================================================================
#define GTM 256
#define GTN 128
#define GBK 32
#define GTS 48
#define GST 4
#define GNKI (DIM / GBK)                                   // 128
#define G_STAGE ((GTM + GTN) * GTS)                        // halves per stage
#define G_SMEM (GST * G_STAGE * 2)                         // 147456 B

__global__ __launch_bounds__(256, 1) void gemm_mma(
    const __half* __restrict__ A,
    const __half* __restrict__ B0, const __half* __restrict__ B1, const __half* __restrict__ B2,
    float* __restrict__ C0, float* __restrict__ C1, float* __restrict__ C2,
    __half* __restrict__ H0, __half* __restrict__ H1,
    const float* __restrict__ rcs, const float* __restrict__ rsn, int is_qkv) {
    extern __shared__ __half smh[];

    const int z = blockIdx.z;
    const __half* B = (z == 0) ? B0 : ((z == 1) ? B1 : B2);
    float*        C = (z == 0) ? C0 : ((z == 1) ? C1 : C2);
    __half*       H = (z == 0) ? H0 : ((z == 1) ? H1 : nullptr);
    const int  mode = is_qkv ? (z + 1) : 0;
    const bool do_rope = is_qkv && (z < 2);

    const int t    = threadIdx.x;
    const int lane = t & 31;
    const int w    = t >> 5;
    const int wm   = w >> 1;          // 0..3
    const int wn   = w & 1;           // 0..1
    const int g    = lane >> 2;       // 0..7
    const int q    = lane & 3;        // 0..3
    const int bm   = blockIdx.y, bn = blockIdx.x;

    const uint32_t sS = smem_u32(smh);
    const int lr  = t >> 2;           // 0..63
    const int lc8 = (t & 3) * 8;      // half offset 0,8,16,24
    const __half* Agp = A + (size_t)(bm * GTM + lr) * DIM + lc8;
    const __half* Bgp = B + (size_t)(bn * GTN + lr) * DIM + lc8;

    float acc[4][8][4];
#pragma unroll
    for (int i = 0; i < 4; i++)
#pragma unroll
        for (int j = 0; j < 8; j++)
#pragma unroll
            for (int v = 0; v < 4; v++) acc[i][j][v] = 0.f;

    // prologue: stages 0..GST-2
#pragma unroll
    for (int s = 0; s < GST - 1; s++) {
        const int k0 = s * GBK;
        const uint32_t dA = sS + s * (G_STAGE * 2);
        const uint32_t dB = dA + GTM * GTS * 2;
#pragma unroll
        for (int j = 0; j < 4; j++)
            cp16(dA + ((lr + j * 64) * GTS + lc8) * 2, Agp + (size_t)(j * 64) * DIM + k0);
#pragma unroll
        for (int j = 0; j < 2; j++)
            cp16(dB + ((lr + j * 64) * GTS + lc8) * 2, Bgp + (size_t)(j * 64) * DIM + k0);
        CP_COMMIT();
    }

    for (int i = 0; i < GNKI; i++) {
        CP_WAIT2();
        __syncthreads();

        if (i + GST - 1 < GNKI) {
            const int st = (i + GST - 1) & (GST - 1);
            const int k0 = (i + GST - 1) * GBK;
            const uint32_t dA = sS + st * (G_STAGE * 2);
            const uint32_t dB = dA + GTM * GTS * 2;
#pragma unroll
            for (int j = 0; j < 4; j++)
                cp16(dA + ((lr + j * 64) * GTS + lc8) * 2, Agp + (size_t)(j * 64) * DIM + k0);
#pragma unroll
            for (int j = 0; j < 2; j++)
                cp16(dB + ((lr + j * 64) * GTS + lc8) * 2, Bgp + (size_t)(j * 64) * DIM + k0);
        }
        CP_COMMIT();   // empty in tail: keeps group accounting valid

        const __half* Ab = smh + (i & (GST - 1)) * G_STAGE;
        const __half* Bb = Ab + GTM * GTS;
#pragma unroll
        for (int s = 0; s < 2; s++) {
            const int ks = s * 16 + 4 * q;        // permuted slot of (2q,2q+1,2q+8,2q+9)
            uint32_t af[4][4], bf[8][2];
#pragma unroll
            for (int mt = 0; mt < 4; mt++) {
                const int r0 = wm * 64 + mt * 16 + g;
                float2 u0 = *(const float2*)(Ab + r0 * GTS + ks);
                float2 u1 = *(const float2*)(Ab + (r0 + 8) * GTS + ks);
                af[mt][0] = __float_as_uint(u0.x);
                af[mt][1] = __float_as_uint(u1.x);
                af[mt][2] = __float_as_uint(u0.y);
                af[mt][3] = __float_as_uint(u1.y);
            }
#pragma unroll
            for (int nt = 0; nt < 8; nt++) {
                const int c0 = wn * 64 + nt * 8 + g;
                float2 v = *(const float2*)(Bb + c0 * GTS + ks);
                bf[nt][0] = __float_as_uint(v.x);
                bf[nt][1] = __float_as_uint(v.y);
            }
#pragma unroll
            for (int mt = 0; mt < 4; mt++)
#pragma unroll
                for (int nt = 0; nt < 8; nt++)
                    mma16n8k16h(acc[mt][nt], af[mt], bf[nt]);
        }
    }

    // epilogue (fused RoPE for Q/K; per-mode fp32/perm-fp16 stores)
#pragma unroll
    for (int mt = 0; mt < 4; mt++) {
        const size_t row = (size_t)bm * GTM + wm * 64 + mt * 16 + g;
#pragma unroll
        for (int nt = 0; nt < 8; nt++) {
            const int col = bn * GTN + wn * 64 + nt * 8 + q * 2;
            float2 v0 = {acc[mt][nt][0], acc[mt][nt][1]};
            float2 v1 = {acc[mt][nt][2], acc[mt][nt][3]};
            if (do_rope) {
                const int fi = (col & 127) >> 1;
                const int s0 = (int)(row & (SEQ - 1));
                const int s1 = (int)((row + 8) & (SEQ - 1));
                float c0 = rcs[s0 * 64 + fi], sn0 = rsn[s0 * 64 + fi];
                float c1 = rcs[s1 * 64 + fi], sn1 = rsn[s1 * 64 + fi];
                float2 r0 = {v0.x * c0 - v0.y * sn0, v0.x * sn0 + v0.y * c0};
                float2 r1 = {v1.x * c1 - v1.y * sn1, v1.x * sn1 + v1.y * c1};
                v0 = r0; v1 = r1;
            }
            if (mode == 0) {
                *(float2*)(C + row * DIM + col)       = v0;
                *(float2*)(C + (row + 8) * DIM + col) = v1;
            } else {
                __half2 h0 = __floats2half2_rn(v0.x, v0.y);
                __half2 h1 = __floats2half2_rn(v1.x, v1.y);
                if (mode != 3) {   // Q or K: perm-fp16 copy
                    const size_t pcol = (size_t)(col & ~15) + 4 * q + 2 * (nt & 1);
                    *(__half2*)(H + row * DIM + pcol)       = h0;
                    *(__half2*)(H + (row + 8) * DIM + pcol) = h1;
                }
                if (mode != 1) {   // K or V: fp32 cache (fp16-rounded values)
                    float2 f0 = {__low2float(h0), __high2float(h0)};
                    float2 f1 = {__low2float(h1), __high2float(h1)};
                    *(float2*)(C + row * DIM + col)       = f0;
                    *(float2*)(C + (row + 8) * DIM + col) = f1;
                }
            }
        }
    }
}

// ============================================================================
// fp16 flash attention (m16n8k16), all-perm layout: every fragment load is
// one LDS.64. BQ=128, BK=64, 8 warps. Output written perm-fp16 straight into
// the WO GEMM's A buffer. __launch_bounds__(256,2): 2 CTAs/SM so one CTA's
// softmax/barriers overlap the other's mma stream (reg cap 128).
// ============================================================================
#define ABQ 128
#define ABK 64
#define QSH 144
#define VTS 80
#define PSH 80
#define FA_SMEM ((ABQ*QSH + 2*ABK*QSH + HD*VTS + 8*16*PSH) * 2)   // 114688 B

__global__ __launch_bounds__(256, 2) void flash_mma(const __half* __restrict__ Qh,
                                                    const __half* __restrict__ Kh,
                                                    const __half* __restrict__ Vt,
                                                    __half* __restrict__ Xt) {
    extern __shared__ __half smA[];
    __half* Qs = smA;                            // 128 x 144
    __half* Kb = Qs + ABQ * QSH;                 // 2 x (64 x 144)
    __half* Vs = Kb + 2 * ABK * QSH;             // 128(d) x 80
    __half* Ps = Vs + HD * VTS;                  // 8 warps x 16 x 80

    const int t    = threadIdx.x;
    const int w    = t >> 5;
    const int lane = t & 31;
    const int g    = lane >> 2;
    const int q    = lane & 3;
    const int qt   = gridDim.x - 1 - blockIdx.x;   // longest tiles first
    const int h    = blockIdx.y, b = blockIdx.z;
    const float scale = 0.08838834764831845f;      // 1/sqrt(128)

    const uint32_t sQs = smem_u32(Qs);
    const uint32_t sKb = smem_u32(Kb);
    const uint32_t sVs = smem_u32(Vs);
    const int nkb = 2 * (qt + 1);

    auto issueK = [&](int kb, int buf) {
        const uint32_t base = sKb + (uint32_t)buf * (ABK * QSH * 2);
        for (int i = t; i < ABK * 16; i += 256) {
            int row = i >> 4, c = i & 15;
            size_t gk = ((size_t)((b * SEQ + kb * ABK + row) * NH + h)) * HD + c * 8;
            cp16(base + (row * QSH + c * 8) * 2, Kh + gk);
        }
    };
    auto issueV = [&](int kb) {
        for (int i = t; i < HD * 8; i += 256) {
            int d = i >> 3, c = i & 7;
            size_t gv = ((size_t)((b * NH + h) * HD + d)) * SEQ + kb * ABK + c * 8;
            cp16(sVs + (d * VTS + c * 8) * 2, Vt + gv);
        }
    };

    // prologue: group0 = K0, group1 = {V0, Q}
    issueK(0, 0); CP_COMMIT();
    issueV(0);
    for (int i = t; i < ABQ * 16; i += 256) {
        int row = i >> 4, c = i & 15;
        size_t gq = ((size_t)((b * SEQ + qt * ABQ + row) * NH + h)) * HD + c * 8;
        cp16(sQs + (row * QSH + c * 8) * 2, Qh + gq);
    }
    CP_COMMIT();

    float o[16][4];
#pragma unroll
    for (int i = 0; i < 16; i++)
#pragma unroll
        for (int v = 0; v < 4; v++) o[i][v] = 0.f;
    float mA = -INFINITY, mB = -INFINITY, lA = 0.f, lB = 0.f;

    __half* Pw = Ps + w * 16 * PSH;
    const int r0   = w * 16;
    const int rowA = qt * ABQ + r0 + g;            // rowB = rowA + 8

    for (int kb = 0; kb < nkb; kb++) {
        if (kb + 1 < nkb) issueK(kb + 1, (kb + 1) & 1);
        CP_COMMIT();
        CP_WAIT1();          // K_kb, V_kb, Q landed
        __syncthreads();

        __half* Kcur = Kb + (kb & 1) * (ABK * QSH);
        const bool full_skip = (kb * ABK > qt * ABQ + r0 + 15);
        if (!full_skip) {
            // ---- S = Q K^T : 8 k16 steps, all LDS.64 ----
            float s[8][4];
#pragma unroll
            for (int i = 0; i < 8; i++)
#pragma unroll
                for (int v = 0; v < 4; v++) s[i][v] = 0.f;
#pragma unroll
            for (int k16 = 0; k16 < 8; k16++) {
                const int ks = k16 * 16 + 4 * q;
                uint32_t a[4];
                float2 u0 = *(const float2*)(Qs + (r0 + g) * QSH + ks);
                float2 u1 = *(const float2*)(Qs + (r0 + g + 8) * QSH + ks);
                a[0] = __float_as_uint(u0.x);
                a[1] = __float_as_uint(u1.x);
                a[2] = __float_as_uint(u0.y);
                a[3] = __float_as_uint(u1.y);
#pragma unroll
                for (int nt = 0; nt < 8; nt++) {
                    float2 v = *(const float2*)(Kcur + (nt * 8 + g) * QSH + ks);
                    uint32_t bfr[2];
                    bfr[0] = __float_as_uint(v.x);
                    bfr[1] = __float_as_uint(v.y);
                    mma16n8k16h(s[nt], a, bfr);
                }
            }
            const bool need_mask = (kb * ABK + ABK - 1 > qt * ABQ + r0);
#pragma unroll
            for (int nt = 0; nt < 8; nt++) {
                const int c0 = kb * ABK + nt * 8 + 2 * q;
                s[nt][0] *= scale; s[nt][1] *= scale;
                s[nt][2] *= scale; s[nt][3] *= scale;
                if (need_mask) {
                    if (c0     > rowA)     s[nt][0] = -1e30f;
                    if (c0 + 1 > rowA)     s[nt][1] = -1e30f;
                    if (c0     > rowA + 8) s[nt][2] = -1e30f;
                    if (c0 + 1 > rowA + 8) s[nt][3] = -1e30f;
                }
            }
            float mxA = -INFINITY, mxB = -INFINITY;
#pragma unroll
            for (int nt = 0; nt < 8; nt++) {
                mxA = fmaxf(mxA, fmaxf(s[nt][0], s[nt][1]));
                mxB = fmaxf(mxB, fmaxf(s[nt][2], s[nt][3]));
            }
            mxA = fmaxf(mxA, __shfl_xor_sync(0xffffffffu, mxA, 1));
            mxA = fmaxf(mxA, __shfl_xor_sync(0xffffffffu, mxA, 2));
            mxB = fmaxf(mxB, __shfl_xor_sync(0xffffffffu, mxB, 1));
            mxB = fmaxf(mxB, __shfl_xor_sync(0xffffffffu, mxB, 2));
            const float mnA = fmaxf(mA, mxA), mnB = fmaxf(mB, mxB);
            const float aA = __expf(mA - mnA), aB = __expf(mB - mnB);
            float sumA = 0.f, sumB = 0.f;
#pragma unroll
            for (int nt = 0; nt < 8; nt++) {
                float p0 = __expf(s[nt][0] - mnA), p1 = __expf(s[nt][1] - mnA);
                float p2 = __expf(s[nt][2] - mnB), p3 = __expf(s[nt][3] - mnB);
                sumA += p0 + p1; sumB += p2 + p3;
                const int po = (nt >> 1) * 16 + 4 * q + 2 * (nt & 1);   // perm slot
                *(uint32_t*)(Pw + g * PSH + po)       = pack_h2(p0, p1);
                *(uint32_t*)(Pw + (g + 8) * PSH + po) = pack_h2(p2, p3);
            }
            sumA += __shfl_xor_sync(0xffffffffu, sumA, 1);
            sumA += __shfl_xor_sync(0xffffffffu, sumA, 2);
            sumB += __shfl_xor_sync(0xffffffffu, sumB, 1);
            sumB += __shfl_xor_sync(0xffffffffu, sumB, 2);
            lA = lA * aA + sumA;  mA = mnA;
            lB = lB * aB + sumB;  mB = mnB;
#pragma unroll
            for (int nt = 0; nt < 16; nt++) {
                o[nt][0] *= aA; o[nt][1] *= aA;
                o[nt][2] *= aB; o[nt][3] *= aB;
            }
            __syncwarp();
            // ---- O += P V : 4 k16 steps, all LDS.64 ----
#pragma unroll
            for (int k16 = 0; k16 < 4; k16++) {
                const int ks = k16 * 16 + 4 * q;
                uint32_t a[4];
                float2 u0 = *(const float2*)(Pw + g * PSH + ks);
                float2 u1 = *(const float2*)(Pw + (g + 8) * PSH + ks);
                a[0] = __float_as_uint(u0.x);
                a[1] = __float_as_uint(u1.x);
                a[2] = __float_as_uint(u0.y);
                a[3] = __float_as_uint(u1.y);
#pragma unroll
                for (int nt = 0; nt < 16; nt++) {
                    float2 v = *(const float2*)(Vs + (nt * 8 + g) * VTS + ks);
                    uint32_t bfr[2];
                    bfr[0] = __float_as_uint(v.x);
                    bfr[1] = __float_as_uint(v.y);
                    mma16n8k16h(o[nt], a, bfr);
                }
            }
        }
        __syncthreads();     // everyone done with Vs before refill

        if (kb + 1 < nkb) issueV(kb + 1);
        CP_COMMIT();
    }

    // write perm-fp16 directly into the WO GEMM's A operand
    const float invA = 1.f / lA, invB = 1.f / lB;
    const size_t baseA = ((size_t)(b * SEQ + rowA)) * DIM + h * HD;
    const size_t baseB = baseA + (size_t)8 * DIM;
#pragma unroll
    for (int ng = 0; ng < 8; ng++) {
        uint2 va = {pack_h2(o[2*ng][0] * invA, o[2*ng][1] * invA),
                    pack_h2(o[2*ng+1][0] * invA, o[2*ng+1][1] * invA)};
        uint2 vb = {pack_h2(o[2*ng][2] * invB, o[2*ng][3] * invB),
                    pack_h2(o[2*ng+1][2] * invB, o[2*ng+1][3] * invB)};
        *(uint2*)(Xt + baseA + ng * 16 + 4 * q) = va;
        *(uint2*)(Xt + baseB + ng * 16 + 4 * q) = vb;
    }
}

// ============================================================================
// launch
// ============================================================================
extern "C" void kernel_launch(void* const* d_in, const int* in_sizes, int n_in,
                              void* d_out, int out_size) {
    const float* x    = (const float*)d_in[0];
    const float* fcos = (const float*)d_in[1];
    const float* fsin = (const float*)d_in[2];
    // d_in[3] mask, d_in[4] input_idexes, d_in[5] cache_k, d_in[6] cache_v: unused
    const float* wq = (const float*)d_in[7];
    const float* wk = (const float*)d_in[8];
    const float* wv = (const float*)d_in[9];
    const float* wo = (const float*)d_in[10];

    float* out     = (float*)d_out;                               // [B,S,DIM]
    float* cache_k = (float*)d_out + (size_t)NTOK * DIM;          // [B,S,NH,HD]
    float* cache_v = (float*)d_out + (size_t)2 * NTOK * DIM;      // [B,S,NH,HD]

    __half* xt;   cudaGetSymbolAddress((void**)&xt,   g_xt);
    __half* wqt;  cudaGetSymbolAddress((void**)&wqt,  g_wqt);
    __half* wkt;  cudaGetSymbolAddress((void**)&wkt,  g_wkt);
    __half* wvt;  cudaGetSymbolAddress((void**)&wvt,  g_wvt);
    __half* wot;  cudaGetSymbolAddress((void**)&wot,  g_wot);
    __half* qh;   cudaGetSymbolAddress((void**)&qh,   g_qh);
    __half* kh;   cudaGetSymbolAddress((void**)&kh,   g_kh);
    __half* vt;   cudaGetSymbolAddress((void**)&vt,   g_vt);

    cudaFuncSetAttribute(gemm_mma,  cudaFuncAttributeMaxDynamicSharedMemorySize, G_SMEM);
    cudaFuncSetAttribute(flash_mma, cudaFuncAttributeMaxDynamicSharedMemorySize, FA_SMEM);

    const int N16 = NTOK * DIM / 16;       // 16-float groups per 64MB buffer
    const int cb = (N16 + 255) / 256;
    dim3 cg(cb, 5);
    cvt_h5<<<cg, 256>>>((const float4*)x, (const float4*)wq, (const float4*)wk,
                        (const float4*)wv, (const float4*)wo,
                        (uint4*)xt, (uint4*)wqt, (uint4*)wkt, (uint4*)wvt, (uint4*)wot,
                        N16);

    // fused QKV: z=0 -> Q (rope, perm-fp16 only), z=1 -> K (rope, fp32+perm-fp16),
    //            z=2 -> V (fp32, fp16-rounded)
    dim3 gq(DIM / GTN, NTOK / GTM, 3);     // (32, 16, 3)
    gemm_mma<<<gq, 256, G_SMEM>>>(xt, wqt, wkt, wvt,
                                  nullptr, cache_k, cache_v,
                                  qh, kh, fcos, fsin, 1);

    // V transpose -> perm-fp16 [b,h,d,s]
    dim3 vg(SEQ / 32, HD / 32, BSZ * NH);  // (64, 4, 64)
    vtrans<<<vg, 256>>>(cache_v, vt);

    // flash writes perm-fp16 attention output straight into xt
    dim3 fg(SEQ / ABQ, NH, BSZ);           // (16, 32, 2)
    flash_mma<<<fg, 256, FA_SMEM>>>(qh, kh, vt, xt);

    dim3 gw(DIM / GTN, NTOK / GTM, 1);     // (32, 16)
    gemm_mma<<<gw, 256, G_SMEM>>>(xt, wot, wot, wot,
                                  out, out, out,
                                  nullptr, nullptr, nullptr, nullptr, 0);
}

// round 16
// speedup vs baseline: 1.1539x; 1.0998x over previous
#include <cuda_runtime.h>
#include <cuda_fp16.h>
#include <math.h>
#include <stdint.h>

#define DIM   4096
#define NH    32
#define HD    128
#define BSZ   2
#define SEQ   2048
#define NTOK  (BSZ*SEQ)          // 4096 tokens

// ---------------- scratch (allocation-free: __device__ globals) -------------
__device__ __half g_xt [(size_t)NTOK * DIM];   // fp16+perm gemm A operand (x, then attn-out)
__device__ __half g_wqt[(size_t)DIM * DIM];    // fp16+perm weights
__device__ __half g_wkt[(size_t)DIM * DIM];
__device__ __half g_wvt[(size_t)DIM * DIM];
__device__ __half g_wot[(size_t)DIM * DIM];
__device__ __half g_qh [(size_t)NTOK * DIM];   // fp16 rotated Q, d-perm  [b,s,h,d]
__device__ __half g_kh [(size_t)NTOK * DIM];   // fp16 rotated K, d-perm  [b,s,h,d]
__device__ __half g_vt [(size_t)NTOK * DIM];   // fp16 V transposed, s-perm [b,h,d,s]

// ============================================================================
// helpers
// ============================================================================
__device__ __forceinline__ uint32_t smem_u32(const void* p) {
    uint32_t a;
    asm("{ .reg .u64 t; cvta.to.shared.u64 t, %1; cvt.u32.u64 %0, t; }"
        : "=r"(a) : "l"(p));
    return a;
}

__device__ __forceinline__ void cp16(uint32_t dst, const void* src) {
    asm volatile("cp.async.cg.shared.global [%0], [%1], 16;" :: "r"(dst), "l"(src));
}
#define CP_COMMIT() asm volatile("cp.async.commit_group;" ::: "memory")
#define CP_WAIT1()  asm volatile("cp.async.wait_group 1;"  ::: "memory")
#define CP_WAIT2()  asm volatile("cp.async.wait_group 2;"  ::: "memory")

__device__ __forceinline__ uint32_t pack_h2(float a, float b) {
    __half2 h = __floats2half2_rn(a, b);
    return *(uint32_t*)&h;
}

// fp16 m16n8k16, fp32 accumulate
__device__ __forceinline__ void mma16n8k16h(float* c, const uint32_t* a, const uint32_t* b) {
    asm volatile(
        "mma.sync.aligned.m16n8k16.row.col.f32.f16.f16.f32 "
        "{%0,%1,%2,%3}, {%4,%5,%6,%7}, {%8,%9}, {%0,%1,%2,%3};"
        : "+f"(c[0]), "+f"(c[1]), "+f"(c[2]), "+f"(c[3])
        : "r"(a[0]), "r"(a[1]), "r"(a[2]), "r"(a[3]), "r"(b[0]), "r"(b[1]));
}

// ============================================================================
// fp32 -> fp16 (rne) + k-group permutation, 5 tensors in ONE launch
// (blockIdx.y selects the tensor). 16-group [l0..l15] -> halves
// [l0,l1,l8,l9, l2,l3,l10,l11, ...]: fragment pair = one aligned float2.
// ============================================================================
__global__ __launch_bounds__(256) void cvt_h5(
    const float4* __restrict__ i0, const float4* __restrict__ i1,
    const float4* __restrict__ i2, const float4* __restrict__ i3,
    const float4* __restrict__ i4,
    uint4* __restrict__ o0, uint4* __restrict__ o1, uint4* __restrict__ o2,
    uint4* __restrict__ o3, uint4* __restrict__ o4, int n16) {
    const int z = blockIdx.y;
    const float4* in = (z == 0) ? i0 : (z == 1) ? i1 : (z == 2) ? i2 : (z == 3) ? i3 : i4;
    uint4* out       = (z == 0) ? o0 : (z == 1) ? o1 : (z == 2) ? o2 : (z == 3) ? o3 : o4;
    int i = blockIdx.x * blockDim.x + threadIdx.x;
    if (i < n16) {
        float4 v0 = in[4 * i], v1 = in[4 * i + 1], v2 = in[4 * i + 2], v3 = in[4 * i + 3];
        uint4 q0, q1;
        q0.x = pack_h2(v0.x, v0.y); q0.y = pack_h2(v2.x, v2.y);
        q0.z = pack_h2(v0.z, v0.w); q0.w = pack_h2(v2.z, v2.w);
        q1.x = pack_h2(v1.x, v1.y); q1.y = pack_h2(v3.x, v3.y);
        q1.z = pack_h2(v1.z, v1.w); q1.w = pack_h2(v3.z, v3.w);
        out[2 * i]     = q0;
        out[2 * i + 1] = q1;
    }
}

// perm of index l within a 16-group: pair p=l/2 -> uint32 slot 2*(p&3)+(p>>2)
__device__ __forceinline__ int perm16(int l) {
    int p = l >> 1;
    return 4 * (p & 3) + 2 * (p >> 2) + (l & 1);
}

// ============================================================================
// V transpose: cache_v fp32 [b,s,h,d] -> g_vt fp16 [b,h,d,s] with s-perm.
// ============================================================================
__global__ __launch_bounds__(256) void vtrans(const float* __restrict__ V,
                                              __half* __restrict__ Vt) {
    __shared__ __half tile[32][33];
    const int tx = threadIdx.x & 31, ty = threadIdx.x >> 5;   // 32 x 8
    const int s0 = blockIdx.x * 32;
    const int d0 = blockIdx.y * 32;
    const int h  = blockIdx.z & (NH - 1);
    const int b  = blockIdx.z >> 5;
#pragma unroll
    for (int j = 0; j < 4; j++) {
        int s = s0 + ty + j * 8;
        tile[ty + j * 8][tx] = __float2half_rn(V[((size_t)((b * SEQ + s) * NH + h)) * HD + d0 + tx]);
    }
    __syncthreads();
    const int sp = s0 + (tx & 16) + perm16(tx & 15);          // permuted s position
#pragma unroll
    for (int j = 0; j < 4; j++) {
        int d = d0 + ty + j * 8;
        Vt[((size_t)((b * NH + h) * HD + d)) * SEQ + sp] = tile[tx][ty + j * 8];
    }
}

// ============================================================================
// fp16 mma.sync GEMM (NT): C[m,n] = sum_k A[m,k]*B[n,k]
// CTA 128x128, 8 warps (2x4), warp tile 64x32, BK=32 halves, 4-stage pipe.
// acc=64 floats/thread -> regs fit 128 -> __launch_bounds__(256,2): 2 CTAs/SM
// (cross-CTA overlap of prologue/barriers/epilogue + wave-tail smoothing).
// mode: 0 = plain fp32 C (WO) | 1 = Q: perm-fp16 H only | 2 = K: fp32 C +
//       perm-fp16 H | 3 = V: fp32 C (fp16-rounded)
// ============================================================================
#define GTM 128
#define GTN 128
#define GBK 32
#define GTS 48
#define GST 4
#define GNKI (DIM / GBK)                                   // 128
#define G_STAGE ((GTM + GTN) * GTS)                        // halves per stage
#define G_SMEM (GST * G_STAGE * 2)                         // 98304 B

__global__ __launch_bounds__(256, 2) void gemm_mma(
    const __half* __restrict__ A,
    const __half* __restrict__ B0, const __half* __restrict__ B1, const __half* __restrict__ B2,
    float* __restrict__ C0, float* __restrict__ C1, float* __restrict__ C2,
    __half* __restrict__ H0, __half* __restrict__ H1,
    const float* __restrict__ rcs, const float* __restrict__ rsn, int is_qkv) {
    extern __shared__ __half smh[];

    const int z = blockIdx.z;
    const __half* B = (z == 0) ? B0 : ((z == 1) ? B1 : B2);
    float*        C = (z == 0) ? C0 : ((z == 1) ? C1 : C2);
    __half*       H = (z == 0) ? H0 : ((z == 1) ? H1 : nullptr);
    const int  mode = is_qkv ? (z + 1) : 0;
    const bool do_rope = is_qkv && (z < 2);

    const int t    = threadIdx.x;
    const int lane = t & 31;
    const int w    = t >> 5;
    const int wm   = w >> 2;          // 0..1  (64-row slab)
    const int wn   = w & 3;           // 0..3  (32-col slab)
    const int g    = lane >> 2;       // 0..7
    const int q    = lane & 3;        // 0..3
    const int bm   = blockIdx.y, bn = blockIdx.x;

    const uint32_t sS = smem_u32(smh);
    const int lr  = t >> 2;           // 0..63
    const int lc8 = (t & 3) * 8;      // half offset 0,8,16,24
    const __half* Agp = A + (size_t)(bm * GTM + lr) * DIM + lc8;
    const __half* Bgp = B + (size_t)(bn * GTN + lr) * DIM + lc8;

    float acc[4][4][4];
#pragma unroll
    for (int i = 0; i < 4; i++)
#pragma unroll
        for (int j = 0; j < 4; j++)
#pragma unroll
            for (int v = 0; v < 4; v++) acc[i][j][v] = 0.f;

    // prologue: stages 0..GST-2
#pragma unroll
    for (int s = 0; s < GST - 1; s++) {
        const int k0 = s * GBK;
        const uint32_t dA = sS + s * (G_STAGE * 2);
        const uint32_t dB = dA + GTM * GTS * 2;
#pragma unroll
        for (int j = 0; j < 2; j++) {
            cp16(dA + ((lr + j * 64) * GTS + lc8) * 2, Agp + (size_t)(j * 64) * DIM + k0);
            cp16(dB + ((lr + j * 64) * GTS + lc8) * 2, Bgp + (size_t)(j * 64) * DIM + k0);
        }
        CP_COMMIT();
    }

    for (int i = 0; i < GNKI; i++) {
        CP_WAIT2();
        __syncthreads();

        if (i + GST - 1 < GNKI) {
            const int st = (i + GST - 1) & (GST - 1);
            const int k0 = (i + GST - 1) * GBK;
            const uint32_t dA = sS + st * (G_STAGE * 2);
            const uint32_t dB = dA + GTM * GTS * 2;
#pragma unroll
            for (int j = 0; j < 2; j++) {
                cp16(dA + ((lr + j * 64) * GTS + lc8) * 2, Agp + (size_t)(j * 64) * DIM + k0);
                cp16(dB + ((lr + j * 64) * GTS + lc8) * 2, Bgp + (size_t)(j * 64) * DIM + k0);
            }
        }
        CP_COMMIT();   // empty in tail: keeps group accounting valid

        const __half* Ab = smh + (i & (GST - 1)) * G_STAGE;
        const __half* Bb = Ab + GTM * GTS;
#pragma unroll
        for (int s = 0; s < 2; s++) {
            const int ks = s * 16 + 4 * q;        // permuted slot of (2q,2q+1,2q+8,2q+9)
            uint32_t af[4][4], bf[4][2];
#pragma unroll
            for (int mt = 0; mt < 4; mt++) {
                const int r0 = wm * 64 + mt * 16 + g;
                float2 u0 = *(const float2*)(Ab + r0 * GTS + ks);
                float2 u1 = *(const float2*)(Ab + (r0 + 8) * GTS + ks);
                af[mt][0] = __float_as_uint(u0.x);
                af[mt][1] = __float_as_uint(u1.x);
                af[mt][2] = __float_as_uint(u0.y);
                af[mt][3] = __float_as_uint(u1.y);
            }
#pragma unroll
            for (int nt = 0; nt < 4; nt++) {
                const int c0 = wn * 32 + nt * 8 + g;
                float2 v = *(const float2*)(Bb + c0 * GTS + ks);
                bf[nt][0] = __float_as_uint(v.x);
                bf[nt][1] = __float_as_uint(v.y);
            }
#pragma unroll
            for (int mt = 0; mt < 4; mt++)
#pragma unroll
                for (int nt = 0; nt < 4; nt++)
                    mma16n8k16h(acc[mt][nt], af[mt], bf[nt]);
        }
    }

    // epilogue (fused RoPE for Q/K; per-mode fp32/perm-fp16 stores)
#pragma unroll
    for (int mt = 0; mt < 4; mt++) {
        const size_t row = (size_t)bm * GTM + wm * 64 + mt * 16 + g;
#pragma unroll
        for (int nt = 0; nt < 4; nt++) {
            const int col = bn * GTN + wn * 32 + nt * 8 + q * 2;
            float2 v0 = {acc[mt][nt][0], acc[mt][nt][1]};
            float2 v1 = {acc[mt][nt][2], acc[mt][nt][3]};
            if (do_rope) {
                const int fi = (col & 127) >> 1;
                const int s0 = (int)(row & (SEQ - 1));
                const int s1 = (int)((row + 8) & (SEQ - 1));
                float c0 = rcs[s0 * 64 + fi], sn0 = rsn[s0 * 64 + fi];
                float c1 = rcs[s1 * 64 + fi], sn1 = rsn[s1 * 64 + fi];
                float2 r0 = {v0.x * c0 - v0.y * sn0, v0.x * sn0 + v0.y * c0};
                float2 r1 = {v1.x * c1 - v1.y * sn1, v1.x * sn1 + v1.y * c1};
                v0 = r0; v1 = r1;
            }
            if (mode == 0) {
                *(float2*)(C + row * DIM + col)       = v0;
                *(float2*)(C + (row + 8) * DIM + col) = v1;
            } else {
                __half2 h0 = __floats2half2_rn(v0.x, v0.y);
                __half2 h1 = __floats2half2_rn(v1.x, v1.y);
                if (mode != 3) {   // Q or K: perm-fp16 copy
                    const size_t pcol = (size_t)(col & ~15) + 4 * q + 2 * (nt & 1);
                    *(__half2*)(H + row * DIM + pcol)       = h0;
                    *(__half2*)(H + (row + 8) * DIM + pcol) = h1;
                }
                if (mode != 1) {   // K or V: fp32 cache (fp16-rounded values)
                    float2 f0 = {__low2float(h0), __high2float(h0)};
                    float2 f1 = {__low2float(h1), __high2float(h1)};
                    *(float2*)(C + row * DIM + col)       = f0;
                    *(float2*)(C + (row + 8) * DIM + col) = f1;
                }
            }
        }
    }
}

// ============================================================================
// fp16 flash attention (m16n8k16), all-perm layout: every fragment load is
// one LDS.64. BQ=128, BK=64, 8 warps, 2 CTAs/SM. Output written perm-fp16
// straight into the WO GEMM's A buffer.
// ============================================================================
#define ABQ 128
#define ABK 64
#define QSH 144
#define VTS 80
#define PSH 80
#define FA_SMEM ((ABQ*QSH + 2*ABK*QSH + HD*VTS + 8*16*PSH) * 2)   // 114688 B

__global__ __launch_bounds__(256, 2) void flash_mma(const __half* __restrict__ Qh,
                                                    const __half* __restrict__ Kh,
                                                    const __half* __restrict__ Vt,
                                                    __half* __restrict__ Xt) {
    extern __shared__ __half smA[];
    __half* Qs = smA;                            // 128 x 144
    __half* Kb = Qs + ABQ * QSH;                 // 2 x (64 x 144)
    __half* Vs = Kb + 2 * ABK * QSH;             // 128(d) x 80
    __half* Ps = Vs + HD * VTS;                  // 8 warps x 16 x 80

    const int t    = threadIdx.x;
    const int w    = t >> 5;
    const int lane = t & 31;
    const int g    = lane >> 2;
    const int q    = lane & 3;
    const int qt   = gridDim.x - 1 - blockIdx.x;   // longest tiles first
    const int h    = blockIdx.y, b = blockIdx.z;
    const float scale = 0.08838834764831845f;      // 1/sqrt(128)

    const uint32_t sQs = smem_u32(Qs);
    const uint32_t sKb = smem_u32(Kb);
    const uint32_t sVs = smem_u32(Vs);
    const int nkb = 2 * (qt + 1);

    auto issueK = [&](int kb, int buf) {
        const uint32_t base = sKb + (uint32_t)buf * (ABK * QSH * 2);
        for (int i = t; i < ABK * 16; i += 256) {
            int row = i >> 4, c = i & 15;
            size_t gk = ((size_t)((b * SEQ + kb * ABK + row) * NH + h)) * HD + c * 8;
            cp16(base + (row * QSH + c * 8) * 2, Kh + gk);
        }
    };
    auto issueV = [&](int kb) {
        for (int i = t; i < HD * 8; i += 256) {
            int d = i >> 3, c = i & 7;
            size_t gv = ((size_t)((b * NH + h) * HD + d)) * SEQ + kb * ABK + c * 8;
            cp16(sVs + (d * VTS + c * 8) * 2, Vt + gv);
        }
    };

    // prologue: group0 = K0, group1 = {V0, Q}
    issueK(0, 0); CP_COMMIT();
    issueV(0);
    for (int i = t; i < ABQ * 16; i += 256) {
        int row = i >> 4, c = i & 15;
        size_t gq = ((size_t)((b * SEQ + qt * ABQ + row) * NH + h)) * HD + c * 8;
        cp16(sQs + (row * QSH + c * 8) * 2, Qh + gq);
    }
    CP_COMMIT();

    float o[16][4];
#pragma unroll
    for (int i = 0; i < 16; i++)
#pragma unroll
        for (int v = 0; v < 4; v++) o[i][v] = 0.f;
    float mA = -INFINITY, mB = -INFINITY, lA = 0.f, lB = 0.f;

    __half* Pw = Ps + w * 16 * PSH;
    const int r0   = w * 16;
    const int rowA = qt * ABQ + r0 + g;            // rowB = rowA + 8

    for (int kb = 0; kb < nkb; kb++) {
        if (kb + 1 < nkb) issueK(kb + 1, (kb + 1) & 1);
        CP_COMMIT();
        CP_WAIT1();          // K_kb, V_kb, Q landed
        __syncthreads();

        __half* Kcur = Kb + (kb & 1) * (ABK * QSH);
        const bool full_skip = (kb * ABK > qt * ABQ + r0 + 15);
        if (!full_skip) {
            // ---- S = Q K^T : 8 k16 steps, all LDS.64 ----
            float s[8][4];
#pragma unroll
            for (int i = 0; i < 8; i++)
#pragma unroll
                for (int v = 0; v < 4; v++) s[i][v] = 0.f;
#pragma unroll
            for (int k16 = 0; k16 < 8; k16++) {
                const int ks = k16 * 16 + 4 * q;
                uint32_t a[4];
                float2 u0 = *(const float2*)(Qs + (r0 + g) * QSH + ks);
                float2 u1 = *(const float2*)(Qs + (r0 + g + 8) * QSH + ks);
                a[0] = __float_as_uint(u0.x);
                a[1] = __float_as_uint(u1.x);
                a[2] = __float_as_uint(u0.y);
                a[3] = __float_as_uint(u1.y);
#pragma unroll
                for (int nt = 0; nt < 8; nt++) {
                    float2 v = *(const float2*)(Kcur + (nt * 8 + g) * QSH + ks);
                    uint32_t bfr[2];
                    bfr[0] = __float_as_uint(v.x);
                    bfr[1] = __float_as_uint(v.y);
                    mma16n8k16h(s[nt], a, bfr);
                }
            }
            const bool need_mask = (kb * ABK + ABK - 1 > qt * ABQ + r0);
#pragma unroll
            for (int nt = 0; nt < 8; nt++) {
                const int c0 = kb * ABK + nt * 8 + 2 * q;
                s[nt][0] *= scale; s[nt][1] *= scale;
                s[nt][2] *= scale; s[nt][3] *= scale;
                if (need_mask) {
                    if (c0     > rowA)     s[nt][0] = -1e30f;
                    if (c0 + 1 > rowA)     s[nt][1] = -1e30f;
                    if (c0     > rowA + 8) s[nt][2] = -1e30f;
                    if (c0 + 1 > rowA + 8) s[nt][3] = -1e30f;
                }
            }
            float mxA = -INFINITY, mxB = -INFINITY;
#pragma unroll
            for (int nt = 0; nt < 8; nt++) {
                mxA = fmaxf(mxA, fmaxf(s[nt][0], s[nt][1]));
                mxB = fmaxf(mxB, fmaxf(s[nt][2], s[nt][3]));
            }
            mxA = fmaxf(mxA, __shfl_xor_sync(0xffffffffu, mxA, 1));
            mxA = fmaxf(mxA, __shfl_xor_sync(0xffffffffu, mxA, 2));
            mxB = fmaxf(mxB, __shfl_xor_sync(0xffffffffu, mxB, 1));
            mxB = fmaxf(mxB, __shfl_xor_sync(0xffffffffu, mxB, 2));
            const float mnA = fmaxf(mA, mxA), mnB = fmaxf(mB, mxB);
            const float aA = __expf(mA - mnA), aB = __expf(mB - mnB);
            float sumA = 0.f, sumB = 0.f;
#pragma unroll
            for (int nt = 0; nt < 8; nt++) {
                float p0 = __expf(s[nt][0] - mnA), p1 = __expf(s[nt][1] - mnA);
                float p2 = __expf(s[nt][2] - mnB), p3 = __expf(s[nt][3] - mnB);
                sumA += p0 + p1; sumB += p2 + p3;
                const int po = (nt >> 1) * 16 + 4 * q + 2 * (nt & 1);   // perm slot
                *(uint32_t*)(Pw + g * PSH + po)       = pack_h2(p0, p1);
                *(uint32_t*)(Pw + (g + 8) * PSH + po) = pack_h2(p2, p3);
            }
            sumA += __shfl_xor_sync(0xffffffffu, sumA, 1);
            sumA += __shfl_xor_sync(0xffffffffu, sumA, 2);
            sumB += __shfl_xor_sync(0xffffffffu, sumB, 1);
            sumB += __shfl_xor_sync(0xffffffffu, sumB, 2);
            lA = lA * aA + sumA;  mA = mnA;
            lB = lB * aB + sumB;  mB = mnB;
#pragma unroll
            for (int nt = 0; nt < 16; nt++) {
                o[nt][0] *= aA; o[nt][1] *= aA;
                o[nt][2] *= aB; o[nt][3] *= aB;
            }
            __syncwarp();
            // ---- O += P V : 4 k16 steps, all LDS.64 ----
#pragma unroll
            for (int k16 = 0; k16 < 4; k16++) {
                const int ks = k16 * 16 + 4 * q;
                uint32_t a[4];
                float2 u0 = *(const float2*)(Pw + g * PSH + ks);
                float2 u1 = *(const float2*)(Pw + (g + 8) * PSH + ks);
                a[0] = __float_as_uint(u0.x);
                a[1] = __float_as_uint(u1.x);
                a[2] = __float_as_uint(u0.y);
                a[3] = __float_as_uint(u1.y);
#pragma unroll
                for (int nt = 0; nt < 16; nt++) {
                    float2 v = *(const float2*)(Vs + (nt * 8 + g) * VTS + ks);
                    uint32_t bfr[2];
                    bfr[0] = __float_as_uint(v.x);
                    bfr[1] = __float_as_uint(v.y);
                    mma16n8k16h(o[nt], a, bfr);
                }
            }
        }
        __syncthreads();     // everyone done with Vs before refill

        if (kb + 1 < nkb) issueV(kb + 1);
        CP_COMMIT();
    }

    // write perm-fp16 directly into the WO GEMM's A operand
    const float invA = 1.f / lA, invB = 1.f / lB;
    const size_t baseA = ((size_t)(b * SEQ + rowA)) * DIM + h * HD;
    const size_t baseB = baseA + (size_t)8 * DIM;
#pragma unroll
    for (int ng = 0; ng < 8; ng++) {
        uint2 va = {pack_h2(o[2*ng][0] * invA, o[2*ng][1] * invA),
                    pack_h2(o[2*ng+1][0] * invA, o[2*ng+1][1] * invA)};
        uint2 vb = {pack_h2(o[2*ng][2] * invB, o[2*ng][3] * invB),
                    pack_h2(o[2*ng+1][2] * invB, o[2*ng+1][3] * invB)};
        *(uint2*)(Xt + baseA + ng * 16 + 4 * q) = va;
        *(uint2*)(Xt + baseB + ng * 16 + 4 * q) = vb;
    }
}

// ============================================================================
// launch
// ============================================================================
extern "C" void kernel_launch(void* const* d_in, const int* in_sizes, int n_in,
                              void* d_out, int out_size) {
    const float* x    = (const float*)d_in[0];
    const float* fcos = (const float*)d_in[1];
    const float* fsin = (const float*)d_in[2];
    // d_in[3] mask, d_in[4] input_idexes, d_in[5] cache_k, d_in[6] cache_v: unused
    const float* wq = (const float*)d_in[7];
    const float* wk = (const float*)d_in[8];
    const float* wv = (const float*)d_in[9];
    const float* wo = (const float*)d_in[10];

    float* out     = (float*)d_out;                               // [B,S,DIM]
    float* cache_k = (float*)d_out + (size_t)NTOK * DIM;          // [B,S,NH,HD]
    float* cache_v = (float*)d_out + (size_t)2 * NTOK * DIM;      // [B,S,NH,HD]

    __half* xt;   cudaGetSymbolAddress((void**)&xt,   g_xt);
    __half* wqt;  cudaGetSymbolAddress((void**)&wqt,  g_wqt);
    __half* wkt;  cudaGetSymbolAddress((void**)&wkt,  g_wkt);
    __half* wvt;  cudaGetSymbolAddress((void**)&wvt,  g_wvt);
    __half* wot;  cudaGetSymbolAddress((void**)&wot,  g_wot);
    __half* qh;   cudaGetSymbolAddress((void**)&qh,   g_qh);
    __half* kh;   cudaGetSymbolAddress((void**)&kh,   g_kh);
    __half* vt;   cudaGetSymbolAddress((void**)&vt,   g_vt);

    cudaFuncSetAttribute(gemm_mma,  cudaFuncAttributeMaxDynamicSharedMemorySize, G_SMEM);
    cudaFuncSetAttribute(flash_mma, cudaFuncAttributeMaxDynamicSharedMemorySize, FA_SMEM);

    const int N16 = NTOK * DIM / 16;       // 16-float groups per 64MB buffer
    const int cb = (N16 + 255) / 256;
    dim3 cg(cb, 5);
    cvt_h5<<<cg, 256>>>((const float4*)x, (const float4*)wq, (const float4*)wk,
                        (const float4*)wv, (const float4*)wo,
                        (uint4*)xt, (uint4*)wqt, (uint4*)wkt, (uint4*)wvt, (uint4*)wot,
                        N16);

    // fused QKV: z=0 -> Q (rope, perm-fp16 only), z=1 -> K (rope, fp32+perm-fp16),
    //            z=2 -> V (fp32, fp16-rounded)
    dim3 gq(DIM / GTN, NTOK / GTM, 3);     // (32, 32, 3)
    gemm_mma<<<gq, 256, G_SMEM>>>(xt, wqt, wkt, wvt,
                                  nullptr, cache_k, cache_v,
                                  qh, kh, fcos, fsin, 1);

    // V transpose -> perm-fp16 [b,h,d,s]
    dim3 vg(SEQ / 32, HD / 32, BSZ * NH);  // (64, 4, 64)
    vtrans<<<vg, 256>>>(cache_v, vt);

    // flash writes perm-fp16 attention output straight into xt
    dim3 fg(SEQ / ABQ, NH, BSZ);           // (16, 32, 2)
    flash_mma<<<fg, 256, FA_SMEM>>>(qh, kh, vt, xt);

    dim3 gw(DIM / GTN, NTOK / GTM, 1);     // (32, 32)
    gemm_mma<<<gw, 256, G_SMEM>>>(xt, wot, wot, wot,
                                  out, out, out,
                                  nullptr, nullptr, nullptr, nullptr, 0);
}